// round 2
// baseline (speedup 1.0000x reference)
#include <cuda_runtime.h>
#include <math.h>

#define RS 132   // row stride (floats) for X/Q/K/V smem tiles (mult of 4 for float4)
#define SS 65    // row stride for attention score matrix S
#define XTS 132  // kernel B Xt row stride (MUST be mult of 4 for float4 stores)

// ---------------------------------------------------------------------------
// Kernel A: per-window fused  LN1 -> QKV -> windowed attention -> proj
// writes x = 0.5*attn_out + input to `out` at original token index.
// One CTA per window: grid = B*NW = 8*512 = 4096, 256 threads.
// ---------------------------------------------------------------------------
__global__ void __launch_bounds__(256, 1) swin_attn_kernel(
    const float* __restrict__ inp,
    const float* __restrict__ qkv_w,
    const float* __restrict__ proj_w,
    const float* __restrict__ proj_b,
    const float* __restrict__ bias_table,
    const float* __restrict__ g1,
    const float* __restrict__ b1,
    float* __restrict__ out)
{
    extern __shared__ float sm[];
    float* Xs = sm;                 // 64*RS : LN'd input, later attention output O
    float* Qs = Xs + 64*RS;
    float* Ks = Qs + 64*RS;
    float* Vs = Ks + 64*RS;
    float* WS = Vs + 64*RS;         // 6144 floats: weight-tile staging / S buffer
    float* bias_s = WS + 6144;      // 484 = 121*4
    int*   lab_s  = (int*)(bias_s + 484);   // 64
    int*   orow_s = lab_s + 64;             // 64

    const int tid = threadIdx.x;
    const int wblk = blockIdx.x;
    const int bb = wblk >> 9;          // sample
    const int wi = wblk & 511;         // window within sample
    const int gx = wi >> 6, gy = (wi >> 3) & 7, gz = wi & 7;

    // stage relative-position bias table (121 x 4)
    for (int i = tid; i < 484; i += 256) bias_s[i] = bias_table[i];

    // per-token original row index + shift-mask label
    if (tid < 64) {
        const int lx = tid >> 4, ly = (tid >> 2) & 3, lz = tid & 3;
        const int px = gx*4 + lx, py = gy*4 + ly, pz = gz*4 + lz;   // rolled frame
        const int ox = (px + 2) & 31, oy = (py + 2) & 31, oz = (pz + 2) & 31;
        orow_s[tid] = ((bb*32 + ox)*32 + oy)*32 + oz;
        const int labx = px < 28 ? 0 : (px < 30 ? 1 : 2);
        const int laby = py < 28 ? 0 : (py < 30 ? 1 : 2);
        const int labz = pz < 28 ? 0 : (pz < 30 ? 1 : 2);
        lab_s[tid] = labx*9 + laby*3 + labz;
    }
    __syncthreads();

    const int warp = tid >> 5, lane = tid & 31;

    // ---- Phase 1: LayerNorm into Xs ----
    {
        const float4 gv = *(const float4*)(g1 + lane*4);
        const float4 bv = *(const float4*)(b1 + lane*4);
        for (int t = warp*8; t < warp*8 + 8; ++t) {
            const float* row = inp + (long)orow_s[t]*128;
            const float4 x4 = *(const float4*)(row + lane*4);
            float s = x4.x + x4.y + x4.z + x4.w;
            float q = x4.x*x4.x + x4.y*x4.y + x4.z*x4.z + x4.w*x4.w;
            #pragma unroll
            for (int o = 16; o; o >>= 1) {
                s += __shfl_xor_sync(0xffffffffu, s, o);
                q += __shfl_xor_sync(0xffffffffu, q, o);
            }
            const float m = s * 0.0078125f;
            const float rstd = rsqrtf(q*0.0078125f - m*m + 1e-5f);
            float4 r;
            r.x = (x4.x - m)*rstd*gv.x + bv.x;
            r.y = (x4.y - m)*rstd*gv.y + bv.y;
            r.z = (x4.z - m)*rstd*gv.z + bv.z;
            r.w = (x4.w - m)*rstd*gv.w + bv.w;
            *(float4*)(Xs + t*RS + lane*4) = r;
        }
    }
    __syncthreads();

    // ---- Phase 2: QKV GEMM  (64x128)@(128x384) ----
    {
        const int rg = tid >> 4;      // rows rg*4 .. rg*4+3
        const int cg = tid & 15;      // cols cg*4 + 64*j + s
        float acc[4][6][4];
        #pragma unroll
        for (int i = 0; i < 4; ++i)
            #pragma unroll
            for (int j = 0; j < 6; ++j)
                #pragma unroll
                for (int s4 = 0; s4 < 4; ++s4) acc[i][j][s4] = 0.f;

        for (int kb = 0; kb < 128; kb += 16) {
            if (kb) __syncthreads();
            for (int i = tid; i < 1536; i += 256)
                ((float4*)WS)[i] = ((const float4*)(qkv_w + kb*384))[i];
            __syncthreads();
            #pragma unroll
            for (int kk = 0; kk < 16; ++kk) {
                const float a0 = Xs[(rg*4+0)*RS + kb + kk];
                const float a1 = Xs[(rg*4+1)*RS + kb + kk];
                const float a2 = Xs[(rg*4+2)*RS + kb + kk];
                const float a3 = Xs[(rg*4+3)*RS + kb + kk];
                const float* wr = WS + kk*384 + cg*4;
                #pragma unroll
                for (int j = 0; j < 6; ++j) {
                    const float4 b4 = *(const float4*)(wr + 64*j);
                    acc[0][j][0] += a0*b4.x; acc[0][j][1] += a0*b4.y; acc[0][j][2] += a0*b4.z; acc[0][j][3] += a0*b4.w;
                    acc[1][j][0] += a1*b4.x; acc[1][j][1] += a1*b4.y; acc[1][j][2] += a1*b4.z; acc[1][j][3] += a1*b4.w;
                    acc[2][j][0] += a2*b4.x; acc[2][j][1] += a2*b4.y; acc[2][j][2] += a2*b4.z; acc[2][j][3] += a2*b4.w;
                    acc[3][j][0] += a3*b4.x; acc[3][j][1] += a3*b4.y; acc[3][j][2] += a3*b4.z; acc[3][j][3] += a3*b4.w;
                }
            }
        }
        const float qscale = 0.17677669529663687f;   // 1/sqrt(32)
        #pragma unroll
        for (int i = 0; i < 4; ++i) {
            const int r = rg*4 + i;
            #pragma unroll
            for (int j = 0; j < 6; ++j) {
                const int col = cg*4 + 64*j;
                float4 v4 = make_float4(acc[i][j][0], acc[i][j][1], acc[i][j][2], acc[i][j][3]);
                if (j < 2) {
                    v4.x *= qscale; v4.y *= qscale; v4.z *= qscale; v4.w *= qscale;
                    *(float4*)(Qs + r*RS + col) = v4;
                } else if (j < 4) {
                    *(float4*)(Ks + r*RS + (col - 128)) = v4;
                } else {
                    *(float4*)(Vs + r*RS + (col - 256)) = v4;
                }
            }
        }
    }
    __syncthreads();

    // ---- Phase 3: attention per head (S -> softmax -> O), O into Xs ----
    {
        const int ai = tid >> 2;     // token row
        const int aq = tid & 3;      // j-group / d-group
        const int li = lab_s[ai];
        const int lxi = ai >> 4, lyi = (ai >> 2) & 3, lzi = ai & 3;
        float* S = WS;               // 64 x SS

        for (int h = 0; h < 4; ++h) {
            float qreg[32];
            #pragma unroll
            for (int d4 = 0; d4 < 8; ++d4) {
                const float4 q4 = *(const float4*)(Qs + ai*RS + h*32 + d4*4);
                qreg[d4*4+0]=q4.x; qreg[d4*4+1]=q4.y; qreg[d4*4+2]=q4.z; qreg[d4*4+3]=q4.w;
            }
            float sv[16];
            #pragma unroll
            for (int jj = 0; jj < 16; ++jj) {
                const int j = aq + 4*jj;
                const float* Kr = Ks + j*RS + h*32;
                float a = 0.f;
                #pragma unroll
                for (int d4 = 0; d4 < 8; ++d4) {
                    const float4 k4 = *(const float4*)(Kr + d4*4);
                    a += qreg[d4*4+0]*k4.x + qreg[d4*4+1]*k4.y + qreg[d4*4+2]*k4.z + qreg[d4*4+3]*k4.w;
                }
                const int lxj = j >> 4, lyj = (j >> 2) & 3, lzj = j & 3;
                const int bidx = 11*(lxi - lxj + 3) + (lyi - lyj + 3) + (lzi - lzj + 3);
                a += bias_s[bidx*4 + h];
                if (lab_s[j] != li) a -= 100.f;
                sv[jj] = a;
            }
            // softmax over the 4-thread group (lanes aq=0..3, aligned in warp)
            float mx = sv[0];
            #pragma unroll
            for (int jj = 1; jj < 16; ++jj) mx = fmaxf(mx, sv[jj]);
            mx = fmaxf(mx, __shfl_xor_sync(0xffffffffu, mx, 1));
            mx = fmaxf(mx, __shfl_xor_sync(0xffffffffu, mx, 2));
            float sum = 0.f;
            #pragma unroll
            for (int jj = 0; jj < 16; ++jj) { sv[jj] = expf(sv[jj] - mx); sum += sv[jj]; }
            sum += __shfl_xor_sync(0xffffffffu, sum, 1);
            sum += __shfl_xor_sync(0xffffffffu, sum, 2);
            const float inv = 1.f / sum;
            #pragma unroll
            for (int jj = 0; jj < 16; ++jj) S[ai*SS + aq + 4*jj] = sv[jj]*inv;
            __syncthreads();

            // O = P @ V_h, thread covers (row ai, cols h*32+aq*8..+7)
            float o[8];
            #pragma unroll
            for (int d = 0; d < 8; ++d) o[d] = 0.f;
            #pragma unroll 8
            for (int j = 0; j < 64; ++j) {
                const float p = S[ai*SS + j];
                const float* Vr = Vs + j*RS + h*32 + aq*8;
                const float4 v0 = *(const float4*)(Vr);
                const float4 v1 = *(const float4*)(Vr + 4);
                o[0]+=p*v0.x; o[1]+=p*v0.y; o[2]+=p*v0.z; o[3]+=p*v0.w;
                o[4]+=p*v1.x; o[5]+=p*v1.y; o[6]+=p*v1.z; o[7]+=p*v1.w;
            }
            *(float4*)(Xs + ai*RS + h*32 + aq*8)     = make_float4(o[0],o[1],o[2],o[3]);
            *(float4*)(Xs + ai*RS + h*32 + aq*8 + 4) = make_float4(o[4],o[5],o[6],o[7]);
            __syncthreads();
        }
    }

    // ---- Phase 4: proj GEMM + residual write to global ----
    {
        const int rg = tid >> 4;
        const int cg = tid & 15;
        float acc[4][2][4];
        #pragma unroll
        for (int i = 0; i < 4; ++i)
            #pragma unroll
            for (int j = 0; j < 2; ++j)
                #pragma unroll
                for (int s4 = 0; s4 < 4; ++s4) acc[i][j][s4] = 0.f;

        for (int kb = 0; kb < 128; kb += 16) {
            __syncthreads();
            for (int i = tid; i < 512; i += 256)
                ((float4*)WS)[i] = ((const float4*)(proj_w + kb*128))[i];
            __syncthreads();
            #pragma unroll
            for (int kk = 0; kk < 16; ++kk) {
                const float a0 = Xs[(rg*4+0)*RS + kb + kk];
                const float a1 = Xs[(rg*4+1)*RS + kb + kk];
                const float a2 = Xs[(rg*4+2)*RS + kb + kk];
                const float a3 = Xs[(rg*4+3)*RS + kb + kk];
                const float* wr = WS + kk*128 + cg*4;
                #pragma unroll
                for (int j = 0; j < 2; ++j) {
                    const float4 b4 = *(const float4*)(wr + 64*j);
                    acc[0][j][0] += a0*b4.x; acc[0][j][1] += a0*b4.y; acc[0][j][2] += a0*b4.z; acc[0][j][3] += a0*b4.w;
                    acc[1][j][0] += a1*b4.x; acc[1][j][1] += a1*b4.y; acc[1][j][2] += a1*b4.z; acc[1][j][3] += a1*b4.w;
                    acc[2][j][0] += a2*b4.x; acc[2][j][1] += a2*b4.y; acc[2][j][2] += a2*b4.z; acc[2][j][3] += a2*b4.w;
                    acc[3][j][0] += a3*b4.x; acc[3][j][1] += a3*b4.y; acc[3][j][2] += a3*b4.z; acc[3][j][3] += a3*b4.w;
                }
            }
        }
        #pragma unroll
        for (int i = 0; i < 4; ++i) {
            const int r = rg*4 + i;
            const long base = (long)orow_s[r]*128;
            #pragma unroll
            for (int j = 0; j < 2; ++j) {
                const int col = cg*4 + 64*j;
                const float4 pb = *(const float4*)(proj_b + col);
                const float4 xin = *(const float4*)(inp + base + col);
                float4 o;
                o.x = 0.5f*(acc[i][j][0] + pb.x) + xin.x;
                o.y = 0.5f*(acc[i][j][1] + pb.y) + xin.y;
                o.z = 0.5f*(acc[i][j][2] + pb.z) + xin.z;
                o.w = 0.5f*(acc[i][j][3] + pb.w) + xin.w;
                *(float4*)(out + base + col) = o;
            }
        }
    }
}

// ---------------------------------------------------------------------------
// Kernel B: in-place row-local  LN2 -> MLP(128->512->128, exact GELU) -> res.
// grid = 262144/32 = 8192 blocks, 256 threads, 32 rows per block.
// ---------------------------------------------------------------------------
__global__ void __launch_bounds__(256, 2) swin_mlp_kernel(
    const float* __restrict__ w1, const float* __restrict__ bb1,
    const float* __restrict__ w2, const float* __restrict__ bb2,
    const float* __restrict__ g2, const float* __restrict__ b2,
    float* __restrict__ io)
{
    extern __shared__ float sm[];
    float* Xt  = sm;                 // 32*XTS LN'd rows (XTS mult of 4!)
    float* h1s = Xt + 32*XTS;        // 32*65 gelu'd hidden chunk
    float* w1s = h1s + 32*65;        // 128*64
    float* w2s = w1s + 8192;         // 64*128

    const int tid = threadIdx.x;
    const long row0 = (long)blockIdx.x * 32;
    const int warp = tid >> 5, lane = tid & 31;

    // LN2 into Xt
    {
        const float4 gv = *(const float4*)(g2 + lane*4);
        const float4 bv = *(const float4*)(b2 + lane*4);
        for (int t = warp*4; t < warp*4 + 4; ++t) {
            const float* row = io + (row0 + t)*128;
            const float4 x4 = *(const float4*)(row + lane*4);
            float s = x4.x + x4.y + x4.z + x4.w;
            float q = x4.x*x4.x + x4.y*x4.y + x4.z*x4.z + x4.w*x4.w;
            #pragma unroll
            for (int o = 16; o; o >>= 1) {
                s += __shfl_xor_sync(0xffffffffu, s, o);
                q += __shfl_xor_sync(0xffffffffu, q, o);
            }
            const float m = s * 0.0078125f;
            const float rstd = rsqrtf(q*0.0078125f - m*m + 1e-5f);
            float4 r;
            r.x = (x4.x - m)*rstd*gv.x + bv.x;
            r.y = (x4.y - m)*rstd*gv.y + bv.y;
            r.z = (x4.z - m)*rstd*gv.z + bv.z;
            r.w = (x4.w - m)*rstd*gv.w + bv.w;
            *(float4*)(Xt + t*XTS + lane*4) = r;
        }
    }

    const int rG  = tid >> 3;        // gemm1 row (0..31)
    const int cG  = tid & 7;         // gemm1 col group: cG*4 + 32*jm
    const int r2  = (tid >> 4) * 2;  // gemm2 rows r2, r2+1
    const int c2g = tid & 15;        // gemm2 col group: c2g*4 + 64*jc

    float acc2[2][2][4];
    #pragma unroll
    for (int i = 0; i < 2; ++i)
        #pragma unroll
        for (int j = 0; j < 2; ++j)
            #pragma unroll
            for (int s4 = 0; s4 < 4; ++s4) acc2[i][j][s4] = 0.f;

    for (int mb = 0; mb < 512; mb += 64) {
        __syncthreads();
        // stage w1 chunk [128][64] and w2 chunk [64][128]
        for (int i = tid; i < 2048; i += 256) {
            const int k = i >> 4, mm = i & 15;
            ((float4*)w1s)[i] = *(const float4*)(w1 + k*512 + mb + mm*4);
        }
        for (int i = tid; i < 2048; i += 256)
            ((float4*)w2s)[i] = ((const float4*)(w2 + mb*128))[i];
        __syncthreads();

        // gemm1: h1 = Xt @ w1chunk   (thread: 1 row x 8 cols)
        float a1acc[2][4];
        #pragma unroll
        for (int j = 0; j < 2; ++j)
            #pragma unroll
            for (int s4 = 0; s4 < 4; ++s4) a1acc[j][s4] = 0.f;
        #pragma unroll 8
        for (int k = 0; k < 128; ++k) {
            const float a = Xt[rG*XTS + k];
            const float* wr = w1s + k*64 + cG*4;
            const float4 b0 = *(const float4*)(wr);
            const float4 b1v = *(const float4*)(wr + 32);
            a1acc[0][0]+=a*b0.x; a1acc[0][1]+=a*b0.y; a1acc[0][2]+=a*b0.z; a1acc[0][3]+=a*b0.w;
            a1acc[1][0]+=a*b1v.x; a1acc[1][1]+=a*b1v.y; a1acc[1][2]+=a*b1v.z; a1acc[1][3]+=a*b1v.w;
        }
        #pragma unroll
        for (int jm = 0; jm < 2; ++jm)
            #pragma unroll
            for (int s4 = 0; s4 < 4; ++s4) {
                const int mcol = cG*4 + 32*jm + s4;
                const float v = a1acc[jm][s4] + __ldg(bb1 + mb + mcol);
                h1s[rG*65 + mcol] = v * 0.5f * (1.f + erff(v * 0.70710678118654752f));
            }
        __syncthreads();

        // gemm2 accumulate: out += gelu(h1) @ w2chunk  (thread: 2 rows x 8 cols)
        #pragma unroll 8
        for (int k = 0; k < 64; ++k) {
            const float a0 = h1s[(r2+0)*65 + k];
            const float a1 = h1s[(r2+1)*65 + k];
            const float* wr = w2s + k*128 + c2g*4;
            #pragma unroll
            for (int jc = 0; jc < 2; ++jc) {
                const float4 b4 = *(const float4*)(wr + 64*jc);
                acc2[0][jc][0]+=a0*b4.x; acc2[0][jc][1]+=a0*b4.y; acc2[0][jc][2]+=a0*b4.z; acc2[0][jc][3]+=a0*b4.w;
                acc2[1][jc][0]+=a1*b4.x; acc2[1][jc][1]+=a1*b4.y; acc2[1][jc][2]+=a1*b4.z; acc2[1][jc][3]+=a1*b4.w;
            }
        }
    }

    // final: io = 0.5*(h2 + bb2) + x   (read-then-write per element, in place)
    #pragma unroll
    for (int i = 0; i < 2; ++i) {
        const long grow = row0 + r2 + i;
        #pragma unroll
        for (int jc = 0; jc < 2; ++jc) {
            const int c = c2g*4 + 64*jc;
            const float4 bbv = *(const float4*)(bb2 + c);
            const float4 xv = *(const float4*)(io + grow*128 + c);
            float4 o;
            o.x = 0.5f*(acc2[i][jc][0] + bbv.x) + xv.x;
            o.y = 0.5f*(acc2[i][jc][1] + bbv.y) + xv.y;
            o.z = 0.5f*(acc2[i][jc][2] + bbv.z) + xv.z;
            o.w = 0.5f*(acc2[i][jc][3] + bbv.w) + xv.w;
            *(float4*)(io + grow*128 + c) = o;
        }
    }
}

// ---------------------------------------------------------------------------
extern "C" void kernel_launch(void* const* d_in, const int* in_sizes, int n_in,
                              void* d_out, int out_size) {
    const float* inputs     = (const float*)d_in[0];
    const float* qkv_w      = (const float*)d_in[1];
    const float* proj_w     = (const float*)d_in[2];
    const float* proj_b     = (const float*)d_in[3];
    const float* bias_table = (const float*)d_in[4];
    const float* g1         = (const float*)d_in[5];
    const float* b1         = (const float*)d_in[6];
    const float* g2         = (const float*)d_in[7];
    const float* b2         = (const float*)d_in[8];
    const float* w1         = (const float*)d_in[9];
    const float* bb1        = (const float*)d_in[10];
    const float* w2         = (const float*)d_in[11];
    const float* bb2        = (const float*)d_in[12];
    float* out = (float*)d_out;

    const int smemA = (4*64*RS + 6144 + 484) * 4 + 128 * 4;            // 162192 B
    const int smemB = (32*XTS + 32*65 + 8192 + 8192) * 4;              // 90752 B

    cudaFuncSetAttribute(swin_attn_kernel, cudaFuncAttributeMaxDynamicSharedMemorySize, smemA);
    cudaFuncSetAttribute(swin_mlp_kernel,  cudaFuncAttributeMaxDynamicSharedMemorySize, smemB);

    swin_attn_kernel<<<4096, 256, smemA>>>(inputs, qkv_w, proj_w, proj_b,
                                           bias_table, g1, b1, out);
    swin_mlp_kernel<<<8192, 256, smemB>>>(w1, bb1, w2, bb2, g2, b2, out);
}

// round 6
// speedup vs baseline: 2.1758x; 2.1758x over previous
#include <cuda_runtime.h>
#include <cuda_fp16.h>
#include <mma.h>
#include <math.h>

using namespace nvcuda;

#define RS 132   // row stride (floats) for X/Q/K/V smem tiles (mult of 4 for float4)
#define SS 65    // row stride for attention score matrix S
#define AS 136   // half-precision tile stride (halfs, mult of 8)
#define FS 136   // f32 scratch stride (floats, mult of 4)

// ---------------------------------------------------------------------------
// Kernel A: per-window fused  LN1 -> QKV -> windowed attention -> proj
// (unchanged from passing round-2 kernel)
// ---------------------------------------------------------------------------
__global__ void __launch_bounds__(256, 1) swin_attn_kernel(
    const float* __restrict__ inp,
    const float* __restrict__ qkv_w,
    const float* __restrict__ proj_w,
    const float* __restrict__ proj_b,
    const float* __restrict__ bias_table,
    const float* __restrict__ g1,
    const float* __restrict__ b1,
    float* __restrict__ out)
{
    extern __shared__ float sm[];
    float* Xs = sm;
    float* Qs = Xs + 64*RS;
    float* Ks = Qs + 64*RS;
    float* Vs = Ks + 64*RS;
    float* WS = Vs + 64*RS;
    float* bias_s = WS + 6144;
    int*   lab_s  = (int*)(bias_s + 484);
    int*   orow_s = lab_s + 64;

    const int tid = threadIdx.x;
    const int wblk = blockIdx.x;
    const int bb = wblk >> 9;
    const int wi = wblk & 511;
    const int gx = wi >> 6, gy = (wi >> 3) & 7, gz = wi & 7;

    for (int i = tid; i < 484; i += 256) bias_s[i] = bias_table[i];

    if (tid < 64) {
        const int lx = tid >> 4, ly = (tid >> 2) & 3, lz = tid & 3;
        const int px = gx*4 + lx, py = gy*4 + ly, pz = gz*4 + lz;
        const int ox = (px + 2) & 31, oy = (py + 2) & 31, oz = (pz + 2) & 31;
        orow_s[tid] = ((bb*32 + ox)*32 + oy)*32 + oz;
        const int labx = px < 28 ? 0 : (px < 30 ? 1 : 2);
        const int laby = py < 28 ? 0 : (py < 30 ? 1 : 2);
        const int labz = pz < 28 ? 0 : (pz < 30 ? 1 : 2);
        lab_s[tid] = labx*9 + laby*3 + labz;
    }
    __syncthreads();

    const int warp = tid >> 5, lane = tid & 31;

    // ---- Phase 1: LayerNorm into Xs ----
    {
        const float4 gv = *(const float4*)(g1 + lane*4);
        const float4 bv = *(const float4*)(b1 + lane*4);
        for (int t = warp*8; t < warp*8 + 8; ++t) {
            const float* row = inp + (long)orow_s[t]*128;
            const float4 x4 = *(const float4*)(row + lane*4);
            float s = x4.x + x4.y + x4.z + x4.w;
            float q = x4.x*x4.x + x4.y*x4.y + x4.z*x4.z + x4.w*x4.w;
            #pragma unroll
            for (int o = 16; o; o >>= 1) {
                s += __shfl_xor_sync(0xffffffffu, s, o);
                q += __shfl_xor_sync(0xffffffffu, q, o);
            }
            const float m = s * 0.0078125f;
            const float rstd = rsqrtf(q*0.0078125f - m*m + 1e-5f);
            float4 r;
            r.x = (x4.x - m)*rstd*gv.x + bv.x;
            r.y = (x4.y - m)*rstd*gv.y + bv.y;
            r.z = (x4.z - m)*rstd*gv.z + bv.z;
            r.w = (x4.w - m)*rstd*gv.w + bv.w;
            *(float4*)(Xs + t*RS + lane*4) = r;
        }
    }
    __syncthreads();

    // ---- Phase 2: QKV GEMM ----
    {
        const int rg = tid >> 4;
        const int cg = tid & 15;
        float acc[4][6][4];
        #pragma unroll
        for (int i = 0; i < 4; ++i)
            #pragma unroll
            for (int j = 0; j < 6; ++j)
                #pragma unroll
                for (int s4 = 0; s4 < 4; ++s4) acc[i][j][s4] = 0.f;

        for (int kb = 0; kb < 128; kb += 16) {
            if (kb) __syncthreads();
            for (int i = tid; i < 1536; i += 256)
                ((float4*)WS)[i] = ((const float4*)(qkv_w + kb*384))[i];
            __syncthreads();
            #pragma unroll
            for (int kk = 0; kk < 16; ++kk) {
                const float a0 = Xs[(rg*4+0)*RS + kb + kk];
                const float a1 = Xs[(rg*4+1)*RS + kb + kk];
                const float a2 = Xs[(rg*4+2)*RS + kb + kk];
                const float a3 = Xs[(rg*4+3)*RS + kb + kk];
                const float* wr = WS + kk*384 + cg*4;
                #pragma unroll
                for (int j = 0; j < 6; ++j) {
                    const float4 b4 = *(const float4*)(wr + 64*j);
                    acc[0][j][0] += a0*b4.x; acc[0][j][1] += a0*b4.y; acc[0][j][2] += a0*b4.z; acc[0][j][3] += a0*b4.w;
                    acc[1][j][0] += a1*b4.x; acc[1][j][1] += a1*b4.y; acc[1][j][2] += a1*b4.z; acc[1][j][3] += a1*b4.w;
                    acc[2][j][0] += a2*b4.x; acc[2][j][1] += a2*b4.y; acc[2][j][2] += a2*b4.z; acc[2][j][3] += a2*b4.w;
                    acc[3][j][0] += a3*b4.x; acc[3][j][1] += a3*b4.y; acc[3][j][2] += a3*b4.z; acc[3][j][3] += a3*b4.w;
                }
            }
        }
        const float qscale = 0.17677669529663687f;
        #pragma unroll
        for (int i = 0; i < 4; ++i) {
            const int r = rg*4 + i;
            #pragma unroll
            for (int j = 0; j < 6; ++j) {
                const int col = cg*4 + 64*j;
                float4 v4 = make_float4(acc[i][j][0], acc[i][j][1], acc[i][j][2], acc[i][j][3]);
                if (j < 2) {
                    v4.x *= qscale; v4.y *= qscale; v4.z *= qscale; v4.w *= qscale;
                    *(float4*)(Qs + r*RS + col) = v4;
                } else if (j < 4) {
                    *(float4*)(Ks + r*RS + (col - 128)) = v4;
                } else {
                    *(float4*)(Vs + r*RS + (col - 256)) = v4;
                }
            }
        }
    }
    __syncthreads();

    // ---- Phase 3: attention ----
    {
        const int ai = tid >> 2;
        const int aq = tid & 3;
        const int li = lab_s[ai];
        const int lxi = ai >> 4, lyi = (ai >> 2) & 3, lzi = ai & 3;
        float* S = WS;

        for (int h = 0; h < 4; ++h) {
            float qreg[32];
            #pragma unroll
            for (int d4 = 0; d4 < 8; ++d4) {
                const float4 q4 = *(const float4*)(Qs + ai*RS + h*32 + d4*4);
                qreg[d4*4+0]=q4.x; qreg[d4*4+1]=q4.y; qreg[d4*4+2]=q4.z; qreg[d4*4+3]=q4.w;
            }
            float sv[16];
            #pragma unroll
            for (int jj = 0; jj < 16; ++jj) {
                const int j = aq + 4*jj;
                const float* Kr = Ks + j*RS + h*32;
                float a = 0.f;
                #pragma unroll
                for (int d4 = 0; d4 < 8; ++d4) {
                    const float4 k4 = *(const float4*)(Kr + d4*4);
                    a += qreg[d4*4+0]*k4.x + qreg[d4*4+1]*k4.y + qreg[d4*4+2]*k4.z + qreg[d4*4+3]*k4.w;
                }
                const int lxj = j >> 4, lyj = (j >> 2) & 3, lzj = j & 3;
                const int bidx = 11*(lxi - lxj + 3) + (lyi - lyj + 3) + (lzi - lzj + 3);
                a += bias_s[bidx*4 + h];
                if (lab_s[j] != li) a -= 100.f;
                sv[jj] = a;
            }
            float mx = sv[0];
            #pragma unroll
            for (int jj = 1; jj < 16; ++jj) mx = fmaxf(mx, sv[jj]);
            mx = fmaxf(mx, __shfl_xor_sync(0xffffffffu, mx, 1));
            mx = fmaxf(mx, __shfl_xor_sync(0xffffffffu, mx, 2));
            float sum = 0.f;
            #pragma unroll
            for (int jj = 0; jj < 16; ++jj) { sv[jj] = expf(sv[jj] - mx); sum += sv[jj]; }
            sum += __shfl_xor_sync(0xffffffffu, sum, 1);
            sum += __shfl_xor_sync(0xffffffffu, sum, 2);
            const float inv = 1.f / sum;
            #pragma unroll
            for (int jj = 0; jj < 16; ++jj) S[ai*SS + aq + 4*jj] = sv[jj]*inv;
            __syncthreads();

            float o[8];
            #pragma unroll
            for (int d = 0; d < 8; ++d) o[d] = 0.f;
            #pragma unroll 8
            for (int j = 0; j < 64; ++j) {
                const float p = S[ai*SS + j];
                const float* Vr = Vs + j*RS + h*32 + aq*8;
                const float4 v0 = *(const float4*)(Vr);
                const float4 v1 = *(const float4*)(Vr + 4);
                o[0]+=p*v0.x; o[1]+=p*v0.y; o[2]+=p*v0.z; o[3]+=p*v0.w;
                o[4]+=p*v1.x; o[5]+=p*v1.y; o[6]+=p*v1.z; o[7]+=p*v1.w;
            }
            *(float4*)(Xs + ai*RS + h*32 + aq*8)     = make_float4(o[0],o[1],o[2],o[3]);
            *(float4*)(Xs + ai*RS + h*32 + aq*8 + 4) = make_float4(o[4],o[5],o[6],o[7]);
            __syncthreads();
        }
    }

    // ---- Phase 4: proj GEMM + residual ----
    {
        const int rg = tid >> 4;
        const int cg = tid & 15;
        float acc[4][2][4];
        #pragma unroll
        for (int i = 0; i < 4; ++i)
            #pragma unroll
            for (int j = 0; j < 2; ++j)
                #pragma unroll
                for (int s4 = 0; s4 < 4; ++s4) acc[i][j][s4] = 0.f;

        for (int kb = 0; kb < 128; kb += 16) {
            __syncthreads();
            for (int i = tid; i < 512; i += 256)
                ((float4*)WS)[i] = ((const float4*)(proj_w + kb*128))[i];
            __syncthreads();
            #pragma unroll
            for (int kk = 0; kk < 16; ++kk) {
                const float a0 = Xs[(rg*4+0)*RS + kb + kk];
                const float a1 = Xs[(rg*4+1)*RS + kb + kk];
                const float a2 = Xs[(rg*4+2)*RS + kb + kk];
                const float a3 = Xs[(rg*4+3)*RS + kb + kk];
                const float* wr = WS + kk*128 + cg*4;
                #pragma unroll
                for (int j = 0; j < 2; ++j) {
                    const float4 b4 = *(const float4*)(wr + 64*j);
                    acc[0][j][0] += a0*b4.x; acc[0][j][1] += a0*b4.y; acc[0][j][2] += a0*b4.z; acc[0][j][3] += a0*b4.w;
                    acc[1][j][0] += a1*b4.x; acc[1][j][1] += a1*b4.y; acc[1][j][2] += a1*b4.z; acc[1][j][3] += a1*b4.w;
                    acc[2][j][0] += a2*b4.x; acc[2][j][1] += a2*b4.y; acc[2][j][2] += a2*b4.z; acc[2][j][3] += a2*b4.w;
                    acc[3][j][0] += a3*b4.x; acc[3][j][1] += a3*b4.y; acc[3][j][2] += a3*b4.z; acc[3][j][3] += a3*b4.w;
                }
            }
        }
        #pragma unroll
        for (int i = 0; i < 4; ++i) {
            const int r = rg*4 + i;
            const long base = (long)orow_s[r]*128;
            #pragma unroll
            for (int j = 0; j < 2; ++j) {
                const int col = cg*4 + 64*j;
                const float4 pb = *(const float4*)(proj_b + col);
                const float4 xin = *(const float4*)(inp + base + col);
                float4 o;
                o.x = 0.5f*(acc[i][j][0] + pb.x) + xin.x;
                o.y = 0.5f*(acc[i][j][1] + pb.y) + xin.y;
                o.z = 0.5f*(acc[i][j][2] + pb.z) + xin.z;
                o.w = 0.5f*(acc[i][j][3] + pb.w) + xin.w;
                *(float4*)(out + base + col) = o;
            }
        }
    }
}

// ---------------------------------------------------------------------------
// Kernel B (NEW): wmma fp16 tensor-core MLP, in place on io.
// CTA = 64 rows. grid = 262144/64 = 4096, 256 threads (8 warps), 2 CTA/SM.
//   LN2 -> fp16 A1[64x128]
//   for each 128-wide hidden chunk (4 chunks):
//     stage w1 chunk fp16 -> Wc ; gemm1 (wmma) -> f32 Ff
//     bias+GELU -> fp16 A2 ; stage w2 chunk -> Wc
//     gemm2 (wmma) accumulating in persistent register fragments
//   epilogue: io = 0.5*(acc + bb2) + io
// ---------------------------------------------------------------------------
__global__ void __launch_bounds__(256, 2) swin_mlp_kernel(
    const float* __restrict__ w1, const float* __restrict__ bb1,
    const float* __restrict__ w2, const float* __restrict__ bb2,
    const float* __restrict__ g2, const float* __restrict__ b2,
    float* __restrict__ io)
{
    extern __shared__ char smraw[];
    __half* A1 = (__half*)smraw;            // 64*AS halfs
    __half* A2 = A1 + 64*AS;                // 64*AS halfs
    __half* Wc = A2 + 64*AS;                // 128*AS halfs (w1c / w2c shared)
    float*  Ff = (float*)(Wc + 128*AS);     // 64*FS floats

    const int tid  = threadIdx.x;
    const int warp = tid >> 5, lane = tid & 31;
    const long row0 = (long)blockIdx.x * 64;

    // ---- LN2 -> fp16 A1 ----
    {
        const float4 gv = *(const float4*)(g2 + lane*4);
        const float4 bv = *(const float4*)(b2 + lane*4);
        for (int t = warp*8; t < warp*8 + 8; ++t) {
            const float* row = io + (row0 + t)*128;
            const float4 x4 = *(const float4*)(row + lane*4);
            float s = x4.x + x4.y + x4.z + x4.w;
            float q = x4.x*x4.x + x4.y*x4.y + x4.z*x4.z + x4.w*x4.w;
            #pragma unroll
            for (int o = 16; o; o >>= 1) {
                s += __shfl_xor_sync(0xffffffffu, s, o);
                q += __shfl_xor_sync(0xffffffffu, q, o);
            }
            const float m = s * 0.0078125f;
            const float rstd = rsqrtf(q*0.0078125f - m*m + 1e-5f);
            __half* dst = A1 + t*AS + lane*4;
            dst[0] = __float2half((x4.x - m)*rstd*gv.x + bv.x);
            dst[1] = __float2half((x4.y - m)*rstd*gv.y + bv.y);
            dst[2] = __float2half((x4.z - m)*rstd*gv.z + bv.z);
            dst[3] = __float2half((x4.w - m)*rstd*gv.w + bv.w);
        }
    }

    // warp tiling: row tile rt (16 rows), 4 col tiles at ct0*16
    const int rt  = warp >> 1;
    const int ct0 = (warp & 1) * 4;

    wmma::fragment<wmma::accumulator, 16, 16, 16, float> acc2[4];
    #pragma unroll
    for (int j = 0; j < 4; ++j) wmma::fill_fragment(acc2[j], 0.f);

    for (int nb = 0; nb < 4; ++nb) {
        __syncthreads();   // protect Wc (prev gemm2) and A2 (prev gemm2 reads)

        // stage w1 chunk: Wc[k][n] = w1[k][nb*128 + n], k=0..127, n=0..127
        for (int idx = tid; idx < 4096; idx += 256) {
            const int k = idx >> 5, cg = idx & 31;
            const float4 v = *(const float4*)(w1 + k*512 + nb*128 + cg*4);
            __half* dst = Wc + k*AS + cg*4;
            dst[0] = __float2half(v.x); dst[1] = __float2half(v.y);
            dst[2] = __float2half(v.z); dst[3] = __float2half(v.w);
        }
        __syncthreads();

        // gemm1: C1 = A1 @ w1c  -> Ff
        {
            wmma::fragment<wmma::accumulator, 16, 16, 16, float> c1[4];
            #pragma unroll
            for (int j = 0; j < 4; ++j) wmma::fill_fragment(c1[j], 0.f);
            #pragma unroll
            for (int ks = 0; ks < 8; ++ks) {
                wmma::fragment<wmma::matrix_a, 16, 16, 16, __half, wmma::row_major> fa;
                wmma::load_matrix_sync(fa, A1 + rt*16*AS + ks*16, AS);
                #pragma unroll
                for (int j = 0; j < 4; ++j) {
                    wmma::fragment<wmma::matrix_b, 16, 16, 16, __half, wmma::row_major> fb;
                    wmma::load_matrix_sync(fb, Wc + ks*16*AS + (ct0+j)*16, AS);
                    wmma::mma_sync(c1[j], fa, fb, c1[j]);
                }
            }
            #pragma unroll
            for (int j = 0; j < 4; ++j)
                wmma::store_matrix_sync(Ff + rt*16*FS + (ct0+j)*16, c1[j], FS, wmma::mem_row_major);
        }
        __syncthreads();

        // bias + exact GELU -> fp16 A2 ; stage w2 chunk -> Wc
        for (int idx = tid; idx < 2048; idx += 256) {
            const int r = idx >> 5, cg = idx & 31;
            const float4 v = *(const float4*)(Ff + r*FS + cg*4);
            const float4 bv = *(const float4*)(bb1 + nb*128 + cg*4);
            float h0 = v.x + bv.x, h1 = v.y + bv.y, h2 = v.z + bv.z, h3 = v.w + bv.w;
            h0 = h0 * 0.5f * (1.f + erff(h0 * 0.70710678118654752f));
            h1 = h1 * 0.5f * (1.f + erff(h1 * 0.70710678118654752f));
            h2 = h2 * 0.5f * (1.f + erff(h2 * 0.70710678118654752f));
            h3 = h3 * 0.5f * (1.f + erff(h3 * 0.70710678118654752f));
            __half* dst = A2 + r*AS + cg*4;
            dst[0] = __float2half(h0); dst[1] = __float2half(h1);
            dst[2] = __float2half(h2); dst[3] = __float2half(h3);
        }
        for (int idx = tid; idx < 4096; idx += 256) {
            const int k = idx >> 5, cg = idx & 31;
            const float4 v = *(const float4*)(w2 + (nb*128 + k)*128 + cg*4);
            __half* dst = Wc + k*AS + cg*4;
            dst[0] = __float2half(v.x); dst[1] = __float2half(v.y);
            dst[2] = __float2half(v.z); dst[3] = __float2half(v.w);
        }
        __syncthreads();

        // gemm2: acc2 += A2 @ w2c
        #pragma unroll
        for (int ks = 0; ks < 8; ++ks) {
            wmma::fragment<wmma::matrix_a, 16, 16, 16, __half, wmma::row_major> fa;
            wmma::load_matrix_sync(fa, A2 + rt*16*AS + ks*16, AS);
            #pragma unroll
            for (int j = 0; j < 4; ++j) {
                wmma::fragment<wmma::matrix_b, 16, 16, 16, __half, wmma::row_major> fb;
                wmma::load_matrix_sync(fb, Wc + ks*16*AS + (ct0+j)*16, AS);
                wmma::mma_sync(acc2[j], fa, fb, acc2[j]);
            }
        }
    }

    // epilogue: acc2 -> Ff, then io = 0.5*(Ff + bb2) + io
    __syncthreads();
    #pragma unroll
    for (int j = 0; j < 4; ++j)
        wmma::store_matrix_sync(Ff + rt*16*FS + (ct0+j)*16, acc2[j], FS, wmma::mem_row_major);
    __syncthreads();

    for (int idx = tid; idx < 2048; idx += 256) {
        const int r = idx >> 5, cg = idx & 31;
        const float4 v  = *(const float4*)(Ff + r*FS + cg*4);
        const float4 bv = *(const float4*)(bb2 + cg*4);
        float* gp = io + (row0 + r)*128 + cg*4;
        const float4 xv = *(const float4*)gp;
        float4 o;
        o.x = 0.5f*(v.x + bv.x) + xv.x;
        o.y = 0.5f*(v.y + bv.y) + xv.y;
        o.z = 0.5f*(v.z + bv.z) + xv.z;
        o.w = 0.5f*(v.w + bv.w) + xv.w;
        *(float4*)gp = o;
    }
}

// ---------------------------------------------------------------------------
extern "C" void kernel_launch(void* const* d_in, const int* in_sizes, int n_in,
                              void* d_out, int out_size) {
    const float* inputs     = (const float*)d_in[0];
    const float* qkv_w      = (const float*)d_in[1];
    const float* proj_w     = (const float*)d_in[2];
    const float* proj_b     = (const float*)d_in[3];
    const float* bias_table = (const float*)d_in[4];
    const float* g1         = (const float*)d_in[5];
    const float* b1         = (const float*)d_in[6];
    const float* g2         = (const float*)d_in[7];
    const float* b2         = (const float*)d_in[8];
    const float* w1         = (const float*)d_in[9];
    const float* bb1        = (const float*)d_in[10];
    const float* w2         = (const float*)d_in[11];
    const float* bb2        = (const float*)d_in[12];
    float* out = (float*)d_out;

    const int smemA = (4*64*RS + 6144 + 484) * 4 + 128 * 4;            // 162192 B
    const int smemB = (64*AS + 64*AS + 128*AS) * 2 + 64*FS * 4;        // 104448 B

    cudaFuncSetAttribute(swin_attn_kernel, cudaFuncAttributeMaxDynamicSharedMemorySize, smemA);
    cudaFuncSetAttribute(swin_mlp_kernel,  cudaFuncAttributeMaxDynamicSharedMemorySize, smemB);

    swin_attn_kernel<<<4096, 256, smemA>>>(inputs, qkv_w, proj_w, proj_b,
                                           bias_table, g1, b1, out);
    swin_mlp_kernel<<<4096, 256, smemB>>>(w1, bb1, w2, bb2, g2, b2, out);
}

// round 7
// speedup vs baseline: 4.4428x; 2.0419x over previous
#include <cuda_runtime.h>
#include <cuda_fp16.h>
#include <mma.h>
#include <math.h>

using namespace nvcuda;

#define AS 136   // fp16 tile stride (halfs, mult of 8)
#define FS 136   // f32 scratch stride (floats, mult of 4)
#define SFS 68   // f32 score stride
#define PS 72    // fp16 P stride (mult of 8)

// ---------------------------------------------------------------------------
// Kernel A v2: per-window fused LN1 -> QKV(wmma) -> attention(wmma S/PV,
// scalar softmax) -> proj(wmma) -> 0.5*out + residual scatter.
// One CTA per window: grid 4096, 256 threads (8 warps).
// ---------------------------------------------------------------------------
__global__ void __launch_bounds__(256, 1) swin_attn_kernel(
    const float* __restrict__ inp,
    const float* __restrict__ qkv_w,
    const float* __restrict__ proj_w,
    const float* __restrict__ proj_b,
    const float* __restrict__ bias_table,
    const float* __restrict__ g1,
    const float* __restrict__ b1,
    float* __restrict__ out)
{
    extern __shared__ char sma[];
    __half* Xh = (__half*)sma;            // 64*AS  (LN'd X; later O fp16)
    __half* Qh = Xh + 64*AS;
    __half* Kh = Qh + 64*AS;
    __half* Vh = Kh + 64*AS;
    __half* Wc = Vh + 64*AS;              // 128*AS halfs  (weight chunk staging)
    float*  Sf = (float*)Wc;              // overlay: 64*SFS f32 scores
    __half* Ph = (__half*)(Sf + 64*SFS);  // overlay: 64*PS halfs probs
    float*  Ff = (float*)(Wc + 128*AS);   // 64*FS f32 scratch
    float*  bias_s = Ff + 64*FS;          // 484
    int*    lab_s  = (int*)(bias_s + 484);
    int*    orow_s = lab_s + 64;

    const int tid = threadIdx.x;
    const int warp = tid >> 5, lane = tid & 31;
    const int wblk = blockIdx.x;
    const int bb = wblk >> 9;
    const int wi = wblk & 511;
    const int gx = wi >> 6, gy = (wi >> 3) & 7, gz = wi & 7;

    for (int i = tid; i < 484; i += 256) bias_s[i] = bias_table[i];

    if (tid < 64) {
        const int lx = tid >> 4, ly = (tid >> 2) & 3, lz = tid & 3;
        const int px = gx*4 + lx, py = gy*4 + ly, pz = gz*4 + lz;
        const int ox = (px + 2) & 31, oy = (py + 2) & 31, oz = (pz + 2) & 31;
        orow_s[tid] = ((bb*32 + ox)*32 + oy)*32 + oz;
        const int labx = px < 28 ? 0 : (px < 30 ? 1 : 2);
        const int laby = py < 28 ? 0 : (py < 30 ? 1 : 2);
        const int labz = pz < 28 ? 0 : (pz < 30 ? 1 : 2);
        lab_s[tid] = labx*9 + laby*3 + labz;
    }
    __syncthreads();

    // ---- Phase 1: LayerNorm -> fp16 Xh ----
    {
        const float4 gv = *(const float4*)(g1 + lane*4);
        const float4 bv = *(const float4*)(b1 + lane*4);
        for (int t = warp*8; t < warp*8 + 8; ++t) {
            const float* row = inp + (long)orow_s[t]*128;
            const float4 x4 = *(const float4*)(row + lane*4);
            float s = x4.x + x4.y + x4.z + x4.w;
            float q = x4.x*x4.x + x4.y*x4.y + x4.z*x4.z + x4.w*x4.w;
            #pragma unroll
            for (int o = 16; o; o >>= 1) {
                s += __shfl_xor_sync(0xffffffffu, s, o);
                q += __shfl_xor_sync(0xffffffffu, q, o);
            }
            const float m = s * 0.0078125f;
            const float rstd = rsqrtf(q*0.0078125f - m*m + 1e-5f);
            __half* dst = Xh + t*AS + lane*4;
            dst[0] = __float2half((x4.x - m)*rstd*gv.x + bv.x);
            dst[1] = __float2half((x4.y - m)*rstd*gv.y + bv.y);
            dst[2] = __float2half((x4.z - m)*rstd*gv.z + bv.z);
            dst[3] = __float2half((x4.w - m)*rstd*gv.w + bv.w);
        }
    }

    const int rt  = warp >> 1;            // 16-row tile for 2-warp-wide tilings
    const int ct0 = (warp & 1) * 4;       // 4 col tiles base (128-wide outputs)

    // ---- Phase 2: QKV via wmma, 3 chunks of 128 cols (Q, K, V) ----
    const float qscale = 0.17677669529663687f;
    for (int c = 0; c < 3; ++c) {
        __syncthreads();
        for (int idx = tid; idx < 4096; idx += 256) {
            const int k = idx >> 5, cg = idx & 31;
            const float4 v = *(const float4*)(qkv_w + k*384 + c*128 + cg*4);
            __half* dst = Wc + k*AS + cg*4;
            dst[0] = __float2half(v.x); dst[1] = __float2half(v.y);
            dst[2] = __float2half(v.z); dst[3] = __float2half(v.w);
        }
        __syncthreads();
        {
            wmma::fragment<wmma::accumulator, 16, 16, 16, float> c1[4];
            #pragma unroll
            for (int j = 0; j < 4; ++j) wmma::fill_fragment(c1[j], 0.f);
            #pragma unroll
            for (int ks = 0; ks < 8; ++ks) {
                wmma::fragment<wmma::matrix_a, 16, 16, 16, __half, wmma::row_major> fa;
                wmma::load_matrix_sync(fa, Xh + rt*16*AS + ks*16, AS);
                #pragma unroll
                for (int j = 0; j < 4; ++j) {
                    wmma::fragment<wmma::matrix_b, 16, 16, 16, __half, wmma::row_major> fb;
                    wmma::load_matrix_sync(fb, Wc + ks*16*AS + (ct0+j)*16, AS);
                    wmma::mma_sync(c1[j], fa, fb, c1[j]);
                }
            }
            #pragma unroll
            for (int j = 0; j < 4; ++j)
                wmma::store_matrix_sync(Ff + rt*16*FS + (ct0+j)*16, c1[j], FS, wmma::mem_row_major);
        }
        __syncthreads();
        __half* dest = (c == 0) ? Qh : (c == 1) ? Kh : Vh;
        const float scale = (c == 0) ? qscale : 1.f;
        for (int idx = tid; idx < 2048; idx += 256) {
            const int r = idx >> 5, cg = idx & 31;
            const float4 v = *(const float4*)(Ff + r*FS + cg*4);
            __half* dst = dest + r*AS + cg*4;
            dst[0] = __float2half(v.x*scale); dst[1] = __float2half(v.y*scale);
            dst[2] = __float2half(v.z*scale); dst[3] = __float2half(v.w*scale);
        }
    }
    __syncthreads();

    // ---- Phase 3: attention per head ----
    {
        const int ai = tid >> 2;     // softmax row
        const int aq = tid & 3;      // 4 threads per row
        const int li = lab_s[ai];
        const int lxi = ai >> 4, lyi = (ai >> 2) & 3, lzi = ai & 3;

        for (int h = 0; h < 4; ++h) {
            // S = Q_h @ K_h^T  (64x64, k=32). warp: row tile rt, col tiles sct0..+1
            {
                const int sct0 = (warp & 1) * 2;
                wmma::fragment<wmma::accumulator, 16, 16, 16, float> sc[2];
                #pragma unroll
                for (int j = 0; j < 2; ++j) wmma::fill_fragment(sc[j], 0.f);
                #pragma unroll
                for (int ks = 0; ks < 2; ++ks) {
                    wmma::fragment<wmma::matrix_a, 16, 16, 16, __half, wmma::row_major> fa;
                    wmma::load_matrix_sync(fa, Qh + rt*16*AS + h*32 + ks*16, AS);
                    #pragma unroll
                    for (int j = 0; j < 2; ++j) {
                        wmma::fragment<wmma::matrix_b, 16, 16, 16, __half, wmma::col_major> fb;
                        wmma::load_matrix_sync(fb, Kh + (sct0+j)*16*AS + h*32 + ks*16, AS);
                        wmma::mma_sync(sc[j], fa, fb, sc[j]);
                    }
                }
                #pragma unroll
                for (int j = 0; j < 2; ++j)
                    wmma::store_matrix_sync(Sf + rt*16*SFS + (sct0+j)*16, sc[j], SFS, wmma::mem_row_major);
            }
            __syncthreads();

            // bias + mask + softmax (f32) -> fp16 Ph
            {
                float sv[16];
                #pragma unroll
                for (int jj = 0; jj < 16; ++jj) {
                    const int j = aq + 4*jj;
                    float a = Sf[ai*SFS + j];
                    const int lxj = j >> 4, lyj = (j >> 2) & 3, lzj = j & 3;
                    const int bidx = 11*(lxi - lxj + 3) + (lyi - lyj + 3) + (lzi - lzj + 3);
                    a += bias_s[bidx*4 + h];
                    if (lab_s[j] != li) a -= 100.f;
                    sv[jj] = a;
                }
                float mx = sv[0];
                #pragma unroll
                for (int jj = 1; jj < 16; ++jj) mx = fmaxf(mx, sv[jj]);
                mx = fmaxf(mx, __shfl_xor_sync(0xffffffffu, mx, 1));
                mx = fmaxf(mx, __shfl_xor_sync(0xffffffffu, mx, 2));
                float sum = 0.f;
                #pragma unroll
                for (int jj = 0; jj < 16; ++jj) { sv[jj] = expf(sv[jj] - mx); sum += sv[jj]; }
                sum += __shfl_xor_sync(0xffffffffu, sum, 1);
                sum += __shfl_xor_sync(0xffffffffu, sum, 2);
                const float inv = 1.f / sum;
                #pragma unroll
                for (int jj = 0; jj < 16; ++jj)
                    Ph[ai*PS + aq + 4*jj] = __float2half(sv[jj]*inv);
            }
            __syncthreads();

            // O_h = P @ V_h  (64x32, k=64). warp: row tile rt, col tile warp&1
            {
                const int ct = warp & 1;
                wmma::fragment<wmma::accumulator, 16, 16, 16, float> oc;
                wmma::fill_fragment(oc, 0.f);
                #pragma unroll
                for (int ks = 0; ks < 4; ++ks) {
                    wmma::fragment<wmma::matrix_a, 16, 16, 16, __half, wmma::row_major> fa;
                    wmma::load_matrix_sync(fa, Ph + rt*16*PS + ks*16, PS);
                    wmma::fragment<wmma::matrix_b, 16, 16, 16, __half, wmma::row_major> fb;
                    wmma::load_matrix_sync(fb, Vh + ks*16*AS + h*32 + ct*16, AS);
                    wmma::mma_sync(oc, fa, fb, oc);
                }
                wmma::store_matrix_sync(Ff + rt*16*FS + h*32 + ct*16, oc, FS, wmma::mem_row_major);
            }
            __syncthreads();
        }
    }

    // O f32 -> fp16 into Xh (Xh free after QKV)
    for (int idx = tid; idx < 2048; idx += 256) {
        const int r = idx >> 5, cg = idx & 31;
        const float4 v = *(const float4*)(Ff + r*FS + cg*4);
        __half* dst = Xh + r*AS + cg*4;
        dst[0] = __float2half(v.x); dst[1] = __float2half(v.y);
        dst[2] = __float2half(v.z); dst[3] = __float2half(v.w);
    }
    __syncthreads();

    // ---- Phase 4: proj via wmma + residual scatter ----
    for (int idx = tid; idx < 4096; idx += 256) {
        const int k = idx >> 5, cg = idx & 31;
        const float4 v = *(const float4*)(proj_w + k*128 + cg*4);
        __half* dst = Wc + k*AS + cg*4;
        dst[0] = __float2half(v.x); dst[1] = __float2half(v.y);
        dst[2] = __float2half(v.z); dst[3] = __float2half(v.w);
    }
    __syncthreads();
    {
        wmma::fragment<wmma::accumulator, 16, 16, 16, float> pc[4];
        #pragma unroll
        for (int j = 0; j < 4; ++j) wmma::fill_fragment(pc[j], 0.f);
        #pragma unroll
        for (int ks = 0; ks < 8; ++ks) {
            wmma::fragment<wmma::matrix_a, 16, 16, 16, __half, wmma::row_major> fa;
            wmma::load_matrix_sync(fa, Xh + rt*16*AS + ks*16, AS);
            #pragma unroll
            for (int j = 0; j < 4; ++j) {
                wmma::fragment<wmma::matrix_b, 16, 16, 16, __half, wmma::row_major> fb;
                wmma::load_matrix_sync(fb, Wc + ks*16*AS + (ct0+j)*16, AS);
                wmma::mma_sync(pc[j], fa, fb, pc[j]);
            }
        }
        #pragma unroll
        for (int j = 0; j < 4; ++j)
            wmma::store_matrix_sync(Ff + rt*16*FS + (ct0+j)*16, pc[j], FS, wmma::mem_row_major);
    }
    __syncthreads();

    for (int idx = tid; idx < 2048; idx += 256) {
        const int r = idx >> 5, cg = idx & 31;
        const long base = (long)orow_s[r]*128;
        const float4 v  = *(const float4*)(Ff + r*FS + cg*4);
        const float4 pb = *(const float4*)(proj_b + cg*4);
        const float4 xin = *(const float4*)(inp + base + cg*4);
        float4 o;
        o.x = 0.5f*(v.x + pb.x) + xin.x;
        o.y = 0.5f*(v.y + pb.y) + xin.y;
        o.z = 0.5f*(v.z + pb.z) + xin.z;
        o.w = 0.5f*(v.w + pb.w) + xin.w;
        *(float4*)(out + base + cg*4) = o;
    }
}

// ---------------------------------------------------------------------------
// Kernel B: wmma fp16 tensor-core MLP, in place on io. (unchanged, passing)
// ---------------------------------------------------------------------------
__global__ void __launch_bounds__(256, 2) swin_mlp_kernel(
    const float* __restrict__ w1, const float* __restrict__ bb1,
    const float* __restrict__ w2, const float* __restrict__ bb2,
    const float* __restrict__ g2, const float* __restrict__ b2,
    float* __restrict__ io)
{
    extern __shared__ char smraw[];
    __half* A1 = (__half*)smraw;
    __half* A2 = A1 + 64*AS;
    __half* Wc = A2 + 64*AS;
    float*  Ff = (float*)(Wc + 128*AS);

    const int tid  = threadIdx.x;
    const int warp = tid >> 5, lane = tid & 31;
    const long row0 = (long)blockIdx.x * 64;

    {
        const float4 gv = *(const float4*)(g2 + lane*4);
        const float4 bv = *(const float4*)(b2 + lane*4);
        for (int t = warp*8; t < warp*8 + 8; ++t) {
            const float* row = io + (row0 + t)*128;
            const float4 x4 = *(const float4*)(row + lane*4);
            float s = x4.x + x4.y + x4.z + x4.w;
            float q = x4.x*x4.x + x4.y*x4.y + x4.z*x4.z + x4.w*x4.w;
            #pragma unroll
            for (int o = 16; o; o >>= 1) {
                s += __shfl_xor_sync(0xffffffffu, s, o);
                q += __shfl_xor_sync(0xffffffffu, q, o);
            }
            const float m = s * 0.0078125f;
            const float rstd = rsqrtf(q*0.0078125f - m*m + 1e-5f);
            __half* dst = A1 + t*AS + lane*4;
            dst[0] = __float2half((x4.x - m)*rstd*gv.x + bv.x);
            dst[1] = __float2half((x4.y - m)*rstd*gv.y + bv.y);
            dst[2] = __float2half((x4.z - m)*rstd*gv.z + bv.z);
            dst[3] = __float2half((x4.w - m)*rstd*gv.w + bv.w);
        }
    }

    const int rt  = warp >> 1;
    const int ct0 = (warp & 1) * 4;

    wmma::fragment<wmma::accumulator, 16, 16, 16, float> acc2[4];
    #pragma unroll
    for (int j = 0; j < 4; ++j) wmma::fill_fragment(acc2[j], 0.f);

    for (int nb = 0; nb < 4; ++nb) {
        __syncthreads();

        for (int idx = tid; idx < 4096; idx += 256) {
            const int k = idx >> 5, cg = idx & 31;
            const float4 v = *(const float4*)(w1 + k*512 + nb*128 + cg*4);
            __half* dst = Wc + k*AS + cg*4;
            dst[0] = __float2half(v.x); dst[1] = __float2half(v.y);
            dst[2] = __float2half(v.z); dst[3] = __float2half(v.w);
        }
        __syncthreads();

        {
            wmma::fragment<wmma::accumulator, 16, 16, 16, float> c1[4];
            #pragma unroll
            for (int j = 0; j < 4; ++j) wmma::fill_fragment(c1[j], 0.f);
            #pragma unroll
            for (int ks = 0; ks < 8; ++ks) {
                wmma::fragment<wmma::matrix_a, 16, 16, 16, __half, wmma::row_major> fa;
                wmma::load_matrix_sync(fa, A1 + rt*16*AS + ks*16, AS);
                #pragma unroll
                for (int j = 0; j < 4; ++j) {
                    wmma::fragment<wmma::matrix_b, 16, 16, 16, __half, wmma::row_major> fb;
                    wmma::load_matrix_sync(fb, Wc + ks*16*AS + (ct0+j)*16, AS);
                    wmma::mma_sync(c1[j], fa, fb, c1[j]);
                }
            }
            #pragma unroll
            for (int j = 0; j < 4; ++j)
                wmma::store_matrix_sync(Ff + rt*16*FS + (ct0+j)*16, c1[j], FS, wmma::mem_row_major);
        }
        __syncthreads();

        for (int idx = tid; idx < 2048; idx += 256) {
            const int r = idx >> 5, cg = idx & 31;
            const float4 v = *(const float4*)(Ff + r*FS + cg*4);
            const float4 bv = *(const float4*)(bb1 + nb*128 + cg*4);
            float h0 = v.x + bv.x, h1 = v.y + bv.y, h2 = v.z + bv.z, h3 = v.w + bv.w;
            h0 = h0 * 0.5f * (1.f + erff(h0 * 0.70710678118654752f));
            h1 = h1 * 0.5f * (1.f + erff(h1 * 0.70710678118654752f));
            h2 = h2 * 0.5f * (1.f + erff(h2 * 0.70710678118654752f));
            h3 = h3 * 0.5f * (1.f + erff(h3 * 0.70710678118654752f));
            __half* dst = A2 + r*AS + cg*4;
            dst[0] = __float2half(h0); dst[1] = __float2half(h1);
            dst[2] = __float2half(h2); dst[3] = __float2half(h3);
        }
        for (int idx = tid; idx < 4096; idx += 256) {
            const int k = idx >> 5, cg = idx & 31;
            const float4 v = *(const float4*)(w2 + (nb*128 + k)*128 + cg*4);
            __half* dst = Wc + k*AS + cg*4;
            dst[0] = __float2half(v.x); dst[1] = __float2half(v.y);
            dst[2] = __float2half(v.z); dst[3] = __float2half(v.w);
        }
        __syncthreads();

        #pragma unroll
        for (int ks = 0; ks < 8; ++ks) {
            wmma::fragment<wmma::matrix_a, 16, 16, 16, __half, wmma::row_major> fa;
            wmma::load_matrix_sync(fa, A2 + rt*16*AS + ks*16, AS);
            #pragma unroll
            for (int j = 0; j < 4; ++j) {
                wmma::fragment<wmma::matrix_b, 16, 16, 16, __half, wmma::row_major> fb;
                wmma::load_matrix_sync(fb, Wc + ks*16*AS + (ct0+j)*16, AS);
                wmma::mma_sync(acc2[j], fa, fb, acc2[j]);
            }
        }
    }

    __syncthreads();
    #pragma unroll
    for (int j = 0; j < 4; ++j)
        wmma::store_matrix_sync(Ff + rt*16*FS + (ct0+j)*16, acc2[j], FS, wmma::mem_row_major);
    __syncthreads();

    for (int idx = tid; idx < 2048; idx += 256) {
        const int r = idx >> 5, cg = idx & 31;
        const float4 v  = *(const float4*)(Ff + r*FS + cg*4);
        const float4 bv = *(const float4*)(bb2 + cg*4);
        float* gp = io + (row0 + r)*128 + cg*4;
        const float4 xv = *(const float4*)gp;
        float4 o;
        o.x = 0.5f*(v.x + bv.x) + xv.x;
        o.y = 0.5f*(v.y + bv.y) + xv.y;
        o.z = 0.5f*(v.z + bv.z) + xv.z;
        o.w = 0.5f*(v.w + bv.w) + xv.w;
        *(float4*)gp = o;
    }
}

// ---------------------------------------------------------------------------
extern "C" void kernel_launch(void* const* d_in, const int* in_sizes, int n_in,
                              void* d_out, int out_size) {
    const float* inputs     = (const float*)d_in[0];
    const float* qkv_w      = (const float*)d_in[1];
    const float* proj_w     = (const float*)d_in[2];
    const float* proj_b     = (const float*)d_in[3];
    const float* bias_table = (const float*)d_in[4];
    const float* g1         = (const float*)d_in[5];
    const float* b1         = (const float*)d_in[6];
    const float* g2         = (const float*)d_in[7];
    const float* b2         = (const float*)d_in[8];
    const float* w1         = (const float*)d_in[9];
    const float* bb1        = (const float*)d_in[10];
    const float* w2         = (const float*)d_in[11];
    const float* bb2        = (const float*)d_in[12];
    float* out = (float*)d_out;

    // Xh,Qh,Kh,Vh (4*64*AS halfs) + Wc (128*AS halfs) + Ff (64*FS f32) + tables
    const int smemA = (4*64*AS)*2 + (128*AS)*2 + (64*FS)*4 + 484*4 + 128*4;  // 141712 B
    const int smemB = (64*AS + 64*AS + 128*AS) * 2 + 64*FS * 4;              // 104448 B

    cudaFuncSetAttribute(swin_attn_kernel, cudaFuncAttributeMaxDynamicSharedMemorySize, smemA);
    cudaFuncSetAttribute(swin_mlp_kernel,  cudaFuncAttributeMaxDynamicSharedMemorySize, smemB);

    swin_attn_kernel<<<4096, 256, smemA>>>(inputs, qkv_w, proj_w, proj_b,
                                           bias_table, g1, b1, out);
    swin_mlp_kernel<<<4096, 256, smemB>>>(w1, bb1, w2, bb2, g2, b2, out);
}

// round 8
// speedup vs baseline: 6.3538x; 1.4301x over previous
#include <cuda_runtime.h>
#include <cuda_fp16.h>
#include <mma.h>
#include <math.h>

using namespace nvcuda;

#define AS 136   // fp16 tile stride (halfs, mult of 8)
#define FS 136   // f32 scratch stride (floats, mult of 4)
#define SFS 68   // f32 score stride
#define PS 72    // fp16 P stride (mult of 8)

// fp16 pre-converted weights (written by cvt_weights_kernel each launch)
__device__ __half g_qkvwh[128*384];
__device__ __half g_projwh[128*128];
__device__ __half g_w1h[128*512];
__device__ __half g_w2h[512*128];

// ---------------------------------------------------------------------------
// Prep: convert all weights fp32 -> fp16 once. 196608 elements, 4/thread.
// ---------------------------------------------------------------------------
__global__ void cvt_weights_kernel(const float* __restrict__ qkv_w,
                                   const float* __restrict__ proj_w,
                                   const float* __restrict__ w1,
                                   const float* __restrict__ w2)
{
    const int i4 = (blockIdx.x*256 + threadIdx.x) * 4;   // grid 192 -> 196608
    const float* src; __half* dst; int off;
    if (i4 < 49152)            { src = qkv_w;  dst = g_qkvwh;  off = i4; }
    else if (i4 < 65536)       { src = proj_w; dst = g_projwh; off = i4 - 49152; }
    else if (i4 < 131072)      { src = w1;     dst = g_w1h;    off = i4 - 65536; }
    else                       { src = w2;     dst = g_w2h;    off = i4 - 131072; }
    const float4 v = *(const float4*)(src + off);
    dst[off+0] = __float2half(v.x); dst[off+1] = __float2half(v.y);
    dst[off+2] = __float2half(v.z); dst[off+3] = __float2half(v.w);
}

// ---------------------------------------------------------------------------
// Kernel A v3: LN1 -> QKV(wmma) -> attention -> proj(wmma), fp16 weights,
// Ff overlaid on Wc, O held in persistent fragments. 2 CTA/SM.
// ---------------------------------------------------------------------------
__global__ void __launch_bounds__(256, 2) swin_attn_kernel(
    const float* __restrict__ inp,
    const float* __restrict__ proj_b,
    const float* __restrict__ bias_table,
    const float* __restrict__ g1,
    const float* __restrict__ b1,
    float* __restrict__ out)
{
    extern __shared__ char sma[];
    __half* Xh = (__half*)sma;            // 64*AS  (LN'd X; later O fp16)
    __half* Qh = Xh + 64*AS;
    __half* Kh = Qh + 64*AS;
    __half* Vh = Kh + 64*AS;
    char*   U  = (char*)(Vh + 64*AS);     // 34816B union: Wc / Ff / Sf+Ph
    __half* Wc = (__half*)U;              // 128*AS halfs
    float*  Ff = (float*)U;               // 64*FS floats
    float*  Sf = (float*)U;               // 64*SFS floats
    __half* Ph = (__half*)(Sf + 64*SFS);  // 64*PS halfs
    float*  bias_s = (float*)(U + 34816); // 484
    int*    lab_s  = (int*)(bias_s + 484);
    int*    orow_s = lab_s + 64;

    const int tid = threadIdx.x;
    const int warp = tid >> 5, lane = tid & 31;
    const int wblk = blockIdx.x;
    const int bb = wblk >> 9;
    const int wi = wblk & 511;
    const int gx = wi >> 6, gy = (wi >> 3) & 7, gz = wi & 7;

    for (int i = tid; i < 484; i += 256) bias_s[i] = bias_table[i];

    if (tid < 64) {
        const int lx = tid >> 4, ly = (tid >> 2) & 3, lz = tid & 3;
        const int px = gx*4 + lx, py = gy*4 + ly, pz = gz*4 + lz;
        const int ox = (px + 2) & 31, oy = (py + 2) & 31, oz = (pz + 2) & 31;
        orow_s[tid] = ((bb*32 + ox)*32 + oy)*32 + oz;
        const int labx = px < 28 ? 0 : (px < 30 ? 1 : 2);
        const int laby = py < 28 ? 0 : (py < 30 ? 1 : 2);
        const int labz = pz < 28 ? 0 : (pz < 30 ? 1 : 2);
        lab_s[tid] = labx*9 + laby*3 + labz;
    }
    __syncthreads();

    // ---- Phase 1: LayerNorm -> fp16 Xh ----
    {
        const float4 gv = *(const float4*)(g1 + lane*4);
        const float4 bv = *(const float4*)(b1 + lane*4);
        for (int t = warp*8; t < warp*8 + 8; ++t) {
            const float* row = inp + (long)orow_s[t]*128;
            const float4 x4 = *(const float4*)(row + lane*4);
            float s = x4.x + x4.y + x4.z + x4.w;
            float q = x4.x*x4.x + x4.y*x4.y + x4.z*x4.z + x4.w*x4.w;
            #pragma unroll
            for (int o = 16; o; o >>= 1) {
                s += __shfl_xor_sync(0xffffffffu, s, o);
                q += __shfl_xor_sync(0xffffffffu, q, o);
            }
            const float m = s * 0.0078125f;
            const float rstd = rsqrtf(q*0.0078125f - m*m + 1e-5f);
            __half* dst = Xh + t*AS + lane*4;
            dst[0] = __float2half((x4.x - m)*rstd*gv.x + bv.x);
            dst[1] = __float2half((x4.y - m)*rstd*gv.y + bv.y);
            dst[2] = __float2half((x4.z - m)*rstd*gv.z + bv.z);
            dst[3] = __float2half((x4.w - m)*rstd*gv.w + bv.w);
        }
    }

    const int rt  = warp >> 1;            // 16-row tile
    const int ct0 = (warp & 1) * 4;       // col-tile base for 128-wide outputs
    const int ct  = warp & 1;

    // ---- Phase 2: QKV via wmma, 3 chunks of 128 cols (Q, K, V) ----
    const float qscale = 0.17677669529663687f;
    for (int c = 0; c < 3; ++c) {
        __syncthreads();    // U free (prev cvt done / tables done)
        for (int idx = tid; idx < 2048; idx += 256) {
            const int k = idx >> 4, u = idx & 15;
            *(uint4*)(Wc + k*AS + u*8) = *(const uint4*)(g_qkvwh + k*384 + c*128 + u*8);
        }
        __syncthreads();
        wmma::fragment<wmma::accumulator, 16, 16, 16, float> c1[4];
        #pragma unroll
        for (int j = 0; j < 4; ++j) wmma::fill_fragment(c1[j], 0.f);
        #pragma unroll
        for (int ks = 0; ks < 8; ++ks) {
            wmma::fragment<wmma::matrix_a, 16, 16, 16, __half, wmma::row_major> fa;
            wmma::load_matrix_sync(fa, Xh + rt*16*AS + ks*16, AS);
            #pragma unroll
            for (int j = 0; j < 4; ++j) {
                wmma::fragment<wmma::matrix_b, 16, 16, 16, __half, wmma::row_major> fb;
                wmma::load_matrix_sync(fb, Wc + ks*16*AS + (ct0+j)*16, AS);
                wmma::mma_sync(c1[j], fa, fb, c1[j]);
            }
        }
        __syncthreads();    // all reads of Wc done -> overlay as Ff
        #pragma unroll
        for (int j = 0; j < 4; ++j)
            wmma::store_matrix_sync(Ff + rt*16*FS + (ct0+j)*16, c1[j], FS, wmma::mem_row_major);
        __syncthreads();
        __half* dest = (c == 0) ? Qh : (c == 1) ? Kh : Vh;
        const float scale = (c == 0) ? qscale : 1.f;
        for (int idx = tid; idx < 2048; idx += 256) {
            const int r = idx >> 5, cg = idx & 31;
            const float4 v = *(const float4*)(Ff + r*FS + cg*4);
            __half* dst = dest + r*AS + cg*4;
            dst[0] = __float2half(v.x*scale); dst[1] = __float2half(v.y*scale);
            dst[2] = __float2half(v.z*scale); dst[3] = __float2half(v.w*scale);
        }
    }
    __syncthreads();        // Ff reads done -> U reusable as Sf/Ph

    // ---- Phase 3: attention; O accumulated in persistent frags ----
    wmma::fragment<wmma::accumulator, 16, 16, 16, float> oc[4];
    {
        const int ai = tid >> 2;
        const int aq = tid & 3;
        const int li = lab_s[ai];
        const int lxi = ai >> 4, lyi = (ai >> 2) & 3, lzi = ai & 3;

        for (int h = 0; h < 4; ++h) {
            // S = Q_h @ K_h^T
            {
                const int sct0 = ct * 2;
                wmma::fragment<wmma::accumulator, 16, 16, 16, float> sc[2];
                #pragma unroll
                for (int j = 0; j < 2; ++j) wmma::fill_fragment(sc[j], 0.f);
                #pragma unroll
                for (int ks = 0; ks < 2; ++ks) {
                    wmma::fragment<wmma::matrix_a, 16, 16, 16, __half, wmma::row_major> fa;
                    wmma::load_matrix_sync(fa, Qh + rt*16*AS + h*32 + ks*16, AS);
                    #pragma unroll
                    for (int j = 0; j < 2; ++j) {
                        wmma::fragment<wmma::matrix_b, 16, 16, 16, __half, wmma::col_major> fb;
                        wmma::load_matrix_sync(fb, Kh + (sct0+j)*16*AS + h*32 + ks*16, AS);
                        wmma::mma_sync(sc[j], fa, fb, sc[j]);
                    }
                }
                #pragma unroll
                for (int j = 0; j < 2; ++j)
                    wmma::store_matrix_sync(Sf + rt*16*SFS + (sct0+j)*16, sc[j], SFS, wmma::mem_row_major);
            }
            __syncthreads();

            // bias + mask + softmax (f32) -> fp16 Ph
            {
                float sv[16];
                #pragma unroll
                for (int jj = 0; jj < 16; ++jj) {
                    const int j = aq + 4*jj;
                    float a = Sf[ai*SFS + j];
                    const int lxj = j >> 4, lyj = (j >> 2) & 3, lzj = j & 3;
                    const int bidx = 11*(lxi - lxj + 3) + (lyi - lyj + 3) + (lzi - lzj + 3);
                    a += bias_s[bidx*4 + h];
                    if (lab_s[j] != li) a -= 100.f;
                    sv[jj] = a;
                }
                float mx = sv[0];
                #pragma unroll
                for (int jj = 1; jj < 16; ++jj) mx = fmaxf(mx, sv[jj]);
                mx = fmaxf(mx, __shfl_xor_sync(0xffffffffu, mx, 1));
                mx = fmaxf(mx, __shfl_xor_sync(0xffffffffu, mx, 2));
                float sum = 0.f;
                #pragma unroll
                for (int jj = 0; jj < 16; ++jj) { sv[jj] = expf(sv[jj] - mx); sum += sv[jj]; }
                sum += __shfl_xor_sync(0xffffffffu, sum, 1);
                sum += __shfl_xor_sync(0xffffffffu, sum, 2);
                const float inv = 1.f / sum;
                #pragma unroll
                for (int jj = 0; jj < 16; ++jj)
                    Ph[ai*PS + aq + 4*jj] = __float2half(sv[jj]*inv);
            }
            __syncthreads();

            // O_h += P @ V_h into persistent frag oc[h]
            wmma::fill_fragment(oc[h], 0.f);
            #pragma unroll
            for (int ks = 0; ks < 4; ++ks) {
                wmma::fragment<wmma::matrix_a, 16, 16, 16, __half, wmma::row_major> fa;
                wmma::load_matrix_sync(fa, Ph + rt*16*PS + ks*16, PS);
                wmma::fragment<wmma::matrix_b, 16, 16, 16, __half, wmma::row_major> fb;
                wmma::load_matrix_sync(fb, Vh + ks*16*AS + h*32 + ct*16, AS);
                wmma::mma_sync(oc[h], fa, fb, oc[h]);
            }
            // no sync: next S-store writes Sf (disjoint from Ph); softmax of
            // next head is fenced by the post-S-store sync.
        }
    }
    __syncthreads();        // Ph reads done -> U reusable as Ff

    // O frags -> Ff -> fp16 Xh
    #pragma unroll
    for (int h = 0; h < 4; ++h)
        wmma::store_matrix_sync(Ff + rt*16*FS + h*32 + ct*16, oc[h], FS, wmma::mem_row_major);
    __syncthreads();
    for (int idx = tid; idx < 2048; idx += 256) {
        const int r = idx >> 5, cg = idx & 31;
        const float4 v = *(const float4*)(Ff + r*FS + cg*4);
        __half* dst = Xh + r*AS + cg*4;
        dst[0] = __float2half(v.x); dst[1] = __float2half(v.y);
        dst[2] = __float2half(v.z); dst[3] = __float2half(v.w);
    }
    __syncthreads();

    // ---- Phase 4: proj via wmma + residual scatter ----
    for (int idx = tid; idx < 2048; idx += 256) {
        const int k = idx >> 4, u = idx & 15;
        *(uint4*)(Wc + k*AS + u*8) = *(const uint4*)(g_projwh + k*128 + u*8);
    }
    __syncthreads();
    {
        wmma::fragment<wmma::accumulator, 16, 16, 16, float> pc[4];
        #pragma unroll
        for (int j = 0; j < 4; ++j) wmma::fill_fragment(pc[j], 0.f);
        #pragma unroll
        for (int ks = 0; ks < 8; ++ks) {
            wmma::fragment<wmma::matrix_a, 16, 16, 16, __half, wmma::row_major> fa;
            wmma::load_matrix_sync(fa, Xh + rt*16*AS + ks*16, AS);
            #pragma unroll
            for (int j = 0; j < 4; ++j) {
                wmma::fragment<wmma::matrix_b, 16, 16, 16, __half, wmma::row_major> fb;
                wmma::load_matrix_sync(fb, Wc + ks*16*AS + (ct0+j)*16, AS);
                wmma::mma_sync(pc[j], fa, fb, pc[j]);
            }
        }
        __syncthreads();    // Wc reads done -> overlay Ff
        #pragma unroll
        for (int j = 0; j < 4; ++j)
            wmma::store_matrix_sync(Ff + rt*16*FS + (ct0+j)*16, pc[j], FS, wmma::mem_row_major);
    }
    __syncthreads();

    for (int idx = tid; idx < 2048; idx += 256) {
        const int r = idx >> 5, cg = idx & 31;
        const long base = (long)orow_s[r]*128;
        const float4 v  = *(const float4*)(Ff + r*FS + cg*4);
        const float4 pb = *(const float4*)(proj_b + cg*4);
        const float4 xin = *(const float4*)(inp + base + cg*4);
        float4 o;
        o.x = 0.5f*(v.x + pb.x) + xin.x;
        o.y = 0.5f*(v.y + pb.y) + xin.y;
        o.z = 0.5f*(v.z + pb.z) + xin.z;
        o.w = 0.5f*(v.w + pb.w) + xin.w;
        *(float4*)(out + base + cg*4) = o;
    }
}

// ---------------------------------------------------------------------------
// Kernel B v2: wmma fp16 MLP, fp16 weights, Ff overlaid on Wc. 3 CTA/SM.
// ---------------------------------------------------------------------------
__global__ void __launch_bounds__(256, 3) swin_mlp_kernel(
    const float* __restrict__ bb1, const float* __restrict__ bb2,
    const float* __restrict__ g2, const float* __restrict__ b2,
    float* __restrict__ io)
{
    extern __shared__ char smraw[];
    __half* A1 = (__half*)smraw;          // 64*AS
    __half* A2 = A1 + 64*AS;              // 64*AS
    char*   U  = (char*)(A2 + 64*AS);     // 34816B union
    __half* Wc = (__half*)U;              // 128*AS halfs
    float*  Ff = (float*)U;               // 64*FS floats

    const int tid  = threadIdx.x;
    const int warp = tid >> 5, lane = tid & 31;
    const long row0 = (long)blockIdx.x * 64;

    {
        const float4 gv = *(const float4*)(g2 + lane*4);
        const float4 bv = *(const float4*)(b2 + lane*4);
        for (int t = warp*8; t < warp*8 + 8; ++t) {
            const float* row = io + (row0 + t)*128;
            const float4 x4 = *(const float4*)(row + lane*4);
            float s = x4.x + x4.y + x4.z + x4.w;
            float q = x4.x*x4.x + x4.y*x4.y + x4.z*x4.z + x4.w*x4.w;
            #pragma unroll
            for (int o = 16; o; o >>= 1) {
                s += __shfl_xor_sync(0xffffffffu, s, o);
                q += __shfl_xor_sync(0xffffffffu, q, o);
            }
            const float m = s * 0.0078125f;
            const float rstd = rsqrtf(q*0.0078125f - m*m + 1e-5f);
            __half* dst = A1 + t*AS + lane*4;
            dst[0] = __float2half((x4.x - m)*rstd*gv.x + bv.x);
            dst[1] = __float2half((x4.y - m)*rstd*gv.y + bv.y);
            dst[2] = __float2half((x4.z - m)*rstd*gv.z + bv.z);
            dst[3] = __float2half((x4.w - m)*rstd*gv.w + bv.w);
        }
    }

    const int rt  = warp >> 1;
    const int ct0 = (warp & 1) * 4;

    wmma::fragment<wmma::accumulator, 16, 16, 16, float> acc2[4];
    #pragma unroll
    for (int j = 0; j < 4; ++j) wmma::fill_fragment(acc2[j], 0.f);

    for (int nb = 0; nb < 4; ++nb) {
        __syncthreads();    // U free (prev gemm2 reads of Wc done)
        for (int idx = tid; idx < 2048; idx += 256) {
            const int k = idx >> 4, u = idx & 15;
            *(uint4*)(Wc + k*AS + u*8) = *(const uint4*)(g_w1h + k*512 + nb*128 + u*8);
        }
        __syncthreads();

        wmma::fragment<wmma::accumulator, 16, 16, 16, float> c1[4];
        #pragma unroll
        for (int j = 0; j < 4; ++j) wmma::fill_fragment(c1[j], 0.f);
        #pragma unroll
        for (int ks = 0; ks < 8; ++ks) {
            wmma::fragment<wmma::matrix_a, 16, 16, 16, __half, wmma::row_major> fa;
            wmma::load_matrix_sync(fa, A1 + rt*16*AS + ks*16, AS);
            #pragma unroll
            for (int j = 0; j < 4; ++j) {
                wmma::fragment<wmma::matrix_b, 16, 16, 16, __half, wmma::row_major> fb;
                wmma::load_matrix_sync(fb, Wc + ks*16*AS + (ct0+j)*16, AS);
                wmma::mma_sync(c1[j], fa, fb, c1[j]);
            }
        }
        __syncthreads();    // Wc reads done -> overlay Ff
        #pragma unroll
        for (int j = 0; j < 4; ++j)
            wmma::store_matrix_sync(Ff + rt*16*FS + (ct0+j)*16, c1[j], FS, wmma::mem_row_major);
        __syncthreads();

        // bias + exact GELU -> fp16 A2
        for (int idx = tid; idx < 2048; idx += 256) {
            const int r = idx >> 5, cg = idx & 31;
            const float4 v = *(const float4*)(Ff + r*FS + cg*4);
            const float4 bv = *(const float4*)(bb1 + nb*128 + cg*4);
            float h0 = v.x + bv.x, h1 = v.y + bv.y, h2 = v.z + bv.z, h3 = v.w + bv.w;
            h0 = h0 * 0.5f * (1.f + erff(h0 * 0.70710678118654752f));
            h1 = h1 * 0.5f * (1.f + erff(h1 * 0.70710678118654752f));
            h2 = h2 * 0.5f * (1.f + erff(h2 * 0.70710678118654752f));
            h3 = h3 * 0.5f * (1.f + erff(h3 * 0.70710678118654752f));
            __half* dst = A2 + r*AS + cg*4;
            dst[0] = __float2half(h0); dst[1] = __float2half(h1);
            dst[2] = __float2half(h2); dst[3] = __float2half(h3);
        }
        __syncthreads();    // Ff reads done -> overlay Wc (w2 chunk)
        for (int idx = tid; idx < 2048; idx += 256) {
            const int k = idx >> 4, u = idx & 15;
            *(uint4*)(Wc + k*AS + u*8) = *(const uint4*)(g_w2h + (nb*128 + k)*128 + u*8);
        }
        __syncthreads();

        #pragma unroll
        for (int ks = 0; ks < 8; ++ks) {
            wmma::fragment<wmma::matrix_a, 16, 16, 16, __half, wmma::row_major> fa;
            wmma::load_matrix_sync(fa, A2 + rt*16*AS + ks*16, AS);
            #pragma unroll
            for (int j = 0; j < 4; ++j) {
                wmma::fragment<wmma::matrix_b, 16, 16, 16, __half, wmma::row_major> fb;
                wmma::load_matrix_sync(fb, Wc + ks*16*AS + (ct0+j)*16, AS);
                wmma::mma_sync(acc2[j], fa, fb, acc2[j]);
            }
        }
    }

    __syncthreads();        // Wc reads done -> overlay Ff
    #pragma unroll
    for (int j = 0; j < 4; ++j)
        wmma::store_matrix_sync(Ff + rt*16*FS + (ct0+j)*16, acc2[j], FS, wmma::mem_row_major);
    __syncthreads();

    for (int idx = tid; idx < 2048; idx += 256) {
        const int r = idx >> 5, cg = idx & 31;
        const float4 v  = *(const float4*)(Ff + r*FS + cg*4);
        const float4 bv = *(const float4*)(bb2 + cg*4);
        float* gp = io + (row0 + r)*128 + cg*4;
        const float4 xv = *(const float4*)gp;
        float4 o;
        o.x = 0.5f*(v.x + bv.x) + xv.x;
        o.y = 0.5f*(v.y + bv.y) + xv.y;
        o.z = 0.5f*(v.z + bv.z) + xv.z;
        o.w = 0.5f*(v.w + bv.w) + xv.w;
        *(float4*)gp = o;
    }
}

// ---------------------------------------------------------------------------
extern "C" void kernel_launch(void* const* d_in, const int* in_sizes, int n_in,
                              void* d_out, int out_size) {
    const float* inputs     = (const float*)d_in[0];
    const float* qkv_w      = (const float*)d_in[1];
    const float* proj_w     = (const float*)d_in[2];
    const float* proj_b     = (const float*)d_in[3];
    const float* bias_table = (const float*)d_in[4];
    const float* g1         = (const float*)d_in[5];
    const float* b1         = (const float*)d_in[6];
    const float* g2         = (const float*)d_in[7];
    const float* b2         = (const float*)d_in[8];
    const float* w1         = (const float*)d_in[9];
    const float* bb1        = (const float*)d_in[10];
    const float* w2         = (const float*)d_in[11];
    const float* bb2        = (const float*)d_in[12];
    float* out = (float*)d_out;

    // A: Xh..Vh (4*64*AS halfs) + U (34816) + tables (484f + 64i + 64i)
    const int smemA = (4*64*AS)*2 + 34816 + 484*4 + 64*4 + 64*4;   // 106896 B
    // B: A1,A2 (2*64*AS halfs) + U (34816)
    const int smemB = (2*64*AS)*2 + 34816;                          // 69632 B

    cudaFuncSetAttribute(swin_attn_kernel, cudaFuncAttributeMaxDynamicSharedMemorySize, smemA);
    cudaFuncSetAttribute(swin_mlp_kernel,  cudaFuncAttributeMaxDynamicSharedMemorySize, smemB);

    cvt_weights_kernel<<<192, 256>>>(qkv_w, proj_w, w1, w2);
    swin_attn_kernel<<<4096, 256, smemA>>>(inputs, proj_b, bias_table, g1, b1, out);
    swin_mlp_kernel<<<4096, 256, smemB>>>(bb1, bb2, g2, b2, out);
}

// round 9
// speedup vs baseline: 7.0854x; 1.1151x over previous
#include <cuda_runtime.h>
#include <cuda_fp16.h>
#include <mma.h>
#include <math.h>

using namespace nvcuda;

#define AS 136    // fp16 tile stride (halfs, mult of 8)
#define FS 136    // f32 scratch stride (floats)
#define SHS 72    // fp16 score row stride (halfs, mult of 8)
#define HB (64*SHS)  // per-head S block (halfs)

// fp16 pre-converted weights (written by cvt_weights_kernel each launch)
__device__ __half g_qkvwh[128*384];
__device__ __half g_projwh[128*128];
__device__ __half g_w1h[128*512];
__device__ __half g_w2h[512*128];

// ---------------------------------------------------------------------------
__global__ void cvt_weights_kernel(const float* __restrict__ qkv_w,
                                   const float* __restrict__ proj_w,
                                   const float* __restrict__ w1,
                                   const float* __restrict__ w2)
{
    const int i4 = (blockIdx.x*256 + threadIdx.x) * 4;   // grid 192 -> 196608
    const float* src; __half* dst; int off;
    if (i4 < 49152)            { src = qkv_w;  dst = g_qkvwh;  off = i4; }
    else if (i4 < 65536)       { src = proj_w; dst = g_projwh; off = i4 - 49152; }
    else if (i4 < 131072)      { src = w1;     dst = g_w1h;    off = i4 - 65536; }
    else                       { src = w2;     dst = g_w2h;    off = i4 - 131072; }
    const float4 v = *(const float4*)(src + off);
    dst[off+0] = __float2half(v.x); dst[off+1] = __float2half(v.y);
    dst[off+2] = __float2half(v.z); dst[off+3] = __float2half(v.w);
}

// ---------------------------------------------------------------------------
// Kernel A v4: LN1 -> QKV(wmma 32x32 tiles) -> all-heads attention (fp16 S,
// in-register softmax, 3 syncs) -> proj(wmma) -> residual scatter. 2 CTA/SM.
// ---------------------------------------------------------------------------
__global__ void __launch_bounds__(256, 2) swin_attn_kernel(
    const float* __restrict__ inp,
    const float* __restrict__ proj_b,
    const float* __restrict__ bias_table,
    const float* __restrict__ g1,
    const float* __restrict__ b1,
    float* __restrict__ out)
{
    extern __shared__ char sma[];
    __half* Xh = (__half*)sma;            // 64*AS  (LN'd X; later O fp16)
    __half* Qh = Xh + 64*AS;
    __half* Kh = Qh + 64*AS;
    __half* Vh = Kh + 64*AS;
    char*   U  = (char*)(Vh + 64*AS);     // 36864B union: Wc / Ff / Sh(4 heads)
    __half* Wc = (__half*)U;              // 128*AS halfs (34816B)
    float*  Ff = (float*)U;               // 64*FS floats (34816B)
    __half* Sh = (__half*)U;              // 4*HB halfs  (36864B)
    float*  bias_s = (float*)(U + 36864); // 484
    int*    lab_s  = (int*)(bias_s + 484);
    int*    orow_s = lab_s + 64;

    const int tid = threadIdx.x;
    const int warp = tid >> 5, lane = tid & 31;
    const int wblk = blockIdx.x;
    const int bb = wblk >> 9;
    const int wi = wblk & 511;
    const int gx = wi >> 6, gy = (wi >> 3) & 7, gz = wi & 7;

    for (int i = tid; i < 484; i += 256) bias_s[i] = bias_table[i];

    if (tid < 64) {
        const int lx = tid >> 4, ly = (tid >> 2) & 3, lz = tid & 3;
        const int px = gx*4 + lx, py = gy*4 + ly, pz = gz*4 + lz;
        const int ox = (px + 2) & 31, oy = (py + 2) & 31, oz = (pz + 2) & 31;
        orow_s[tid] = ((bb*32 + ox)*32 + oy)*32 + oz;
        const int labx = px < 28 ? 0 : (px < 30 ? 1 : 2);
        const int laby = py < 28 ? 0 : (py < 30 ? 1 : 2);
        const int labz = pz < 28 ? 0 : (pz < 30 ? 1 : 2);
        lab_s[tid] = labx*9 + laby*3 + labz;
    }
    __syncthreads();

    // ---- Phase 1: LayerNorm -> fp16 Xh ----
    {
        const float4 gv = *(const float4*)(g1 + lane*4);
        const float4 bv = *(const float4*)(b1 + lane*4);
        for (int t = warp*8; t < warp*8 + 8; ++t) {
            const float* row = inp + (long)orow_s[t]*128;
            const float4 x4 = *(const float4*)(row + lane*4);
            float s = x4.x + x4.y + x4.z + x4.w;
            float q = x4.x*x4.x + x4.y*x4.y + x4.z*x4.z + x4.w*x4.w;
            #pragma unroll
            for (int o = 16; o; o >>= 1) {
                s += __shfl_xor_sync(0xffffffffu, s, o);
                q += __shfl_xor_sync(0xffffffffu, q, o);
            }
            const float m = s * 0.0078125f;
            const float rstd = rsqrtf(q*0.0078125f - m*m + 1e-5f);
            __half* dst = Xh + t*AS + lane*4;
            dst[0] = __float2half((x4.x - m)*rstd*gv.x + bv.x);
            dst[1] = __float2half((x4.y - m)*rstd*gv.y + bv.y);
            dst[2] = __float2half((x4.z - m)*rstd*gv.z + bv.z);
            dst[3] = __float2half((x4.w - m)*rstd*gv.w + bv.w);
        }
    }

    const int rt2 = warp >> 2;            // 32-row half (0..1)
    const int ct2 = warp & 3;             // 32-col quarter (0..3)

    // ---- Phase 2: QKV via wmma (32x32 warp tiles), 3 chunks ----
    const float qscale = 0.17677669529663687f;
    for (int c = 0; c < 3; ++c) {
        __syncthreads();
        for (int idx = tid; idx < 2048; idx += 256) {
            const int k = idx >> 4, u = idx & 15;
            *(uint4*)(Wc + k*AS + u*8) = *(const uint4*)(g_qkvwh + k*384 + c*128 + u*8);
        }
        __syncthreads();
        wmma::fragment<wmma::accumulator, 16, 16, 16, float> c1[2][2];
        #pragma unroll
        for (int i = 0; i < 2; ++i)
            #pragma unroll
            for (int j = 0; j < 2; ++j) wmma::fill_fragment(c1[i][j], 0.f);
        #pragma unroll
        for (int ks = 0; ks < 8; ++ks) {
            wmma::fragment<wmma::matrix_a, 16, 16, 16, __half, wmma::row_major> fa[2];
            wmma::fragment<wmma::matrix_b, 16, 16, 16, __half, wmma::row_major> fb[2];
            #pragma unroll
            for (int i = 0; i < 2; ++i)
                wmma::load_matrix_sync(fa[i], Xh + (rt2*32 + i*16)*AS + ks*16, AS);
            #pragma unroll
            for (int j = 0; j < 2; ++j)
                wmma::load_matrix_sync(fb[j], Wc + ks*16*AS + ct2*32 + j*16, AS);
            #pragma unroll
            for (int i = 0; i < 2; ++i)
                #pragma unroll
                for (int j = 0; j < 2; ++j) wmma::mma_sync(c1[i][j], fa[i], fb[j], c1[i][j]);
        }
        __syncthreads();    // Wc reads done -> overlay Ff
        #pragma unroll
        for (int i = 0; i < 2; ++i)
            #pragma unroll
            for (int j = 0; j < 2; ++j)
                wmma::store_matrix_sync(Ff + (rt2*32 + i*16)*FS + ct2*32 + j*16, c1[i][j], FS, wmma::mem_row_major);
        __syncthreads();
        __half* dest = (c == 0) ? Qh : (c == 1) ? Kh : Vh;
        const float scale = (c == 0) ? qscale : 1.f;
        for (int idx = tid; idx < 2048; idx += 256) {
            const int r = idx >> 5, cg = idx & 31;
            const float4 v = *(const float4*)(Ff + r*FS + cg*4);
            __half* dst = dest + r*AS + cg*4;
            dst[0] = __float2half(v.x*scale); dst[1] = __float2half(v.y*scale);
            dst[2] = __float2half(v.z*scale); dst[3] = __float2half(v.w*scale);
        }
    }
    __syncthreads();        // Ff reads done -> U reusable as Sh

    // ---- Phase 3: all-heads attention ----
    // S (all 4 heads) via fp16-accum wmma: warp w -> head w>>1, row-half w&1
    {
        const int h = warp >> 1;
        const int p = warp & 1;
        wmma::fragment<wmma::accumulator, 16, 16, 16, __half> sc[2][4];
        #pragma unroll
        for (int i = 0; i < 2; ++i)
            #pragma unroll
            for (int j = 0; j < 4; ++j) wmma::fill_fragment(sc[i][j], __float2half(0.f));
        #pragma unroll
        for (int ks = 0; ks < 2; ++ks) {
            wmma::fragment<wmma::matrix_a, 16, 16, 16, __half, wmma::row_major> fa[2];
            wmma::fragment<wmma::matrix_b, 16, 16, 16, __half, wmma::col_major> fb[4];
            #pragma unroll
            for (int i = 0; i < 2; ++i)
                wmma::load_matrix_sync(fa[i], Qh + (p*32 + i*16)*AS + h*32 + ks*16, AS);
            #pragma unroll
            for (int j = 0; j < 4; ++j)
                wmma::load_matrix_sync(fb[j], Kh + j*16*AS + h*32 + ks*16, AS);
            #pragma unroll
            for (int i = 0; i < 2; ++i)
                #pragma unroll
                for (int j = 0; j < 4; ++j) wmma::mma_sync(sc[i][j], fa[i], fb[j], sc[i][j]);
        }
        #pragma unroll
        for (int i = 0; i < 2; ++i)
            #pragma unroll
            for (int j = 0; j < 4; ++j)
                wmma::store_matrix_sync(Sh + h*HB + (p*32 + i*16)*SHS + j*16, sc[i][j], SHS, wmma::mem_row_major);
    }
    __syncthreads();

    // softmax: one thread per (head, row), fully in registers (half2)
    {
        const int shh = tid >> 6;       // head
        const int si  = tid & 63;       // row
        __half* Srow = Sh + shh*HB + si*SHS;
        const int li = lab_s[si];
        const int lxi = si >> 4, lyi = (si >> 2) & 3, lzi = si & 3;
        half2 av[32];
        float mx = -1e30f;
        #pragma unroll
        for (int t = 0; t < 32; ++t) {
            const int j0 = 2*t;
            const float2 s2 = __half22float2(*(half2*)(Srow + j0));
            const int lxj = j0 >> 4, lyj = (j0 >> 2) & 3, lzj = j0 & 3;
            const int brow = 11*(lxi - lxj + 3) + (lyi - lyj + 3) + (lzi - lzj + 3);
            float a0 = s2.x + bias_s[brow*4 + shh];
            float a1 = s2.y + bias_s[(brow-1)*4 + shh];
            if (lab_s[j0]   != li) a0 -= 100.f;
            if (lab_s[j0+1] != li) a1 -= 100.f;
            mx = fmaxf(mx, fmaxf(a0, a1));
            av[t] = __floats2half2_rn(a0, a1);
        }
        const half2 mx2 = __float2half2_rn(mx);
        float sum = 0.f;
        #pragma unroll
        for (int t = 0; t < 32; ++t) {
            av[t] = h2exp(__hsub2(av[t], mx2));
            const float2 e2 = __half22float2(av[t]);
            sum += e2.x + e2.y;
        }
        const half2 inv2 = __float2half2_rn(1.f / sum);
        #pragma unroll
        for (int t = 0; t < 32; ++t)
            *(half2*)(Srow + 2*t) = __hmul2(av[t], inv2);
    }
    __syncthreads();

    // PV (all heads): warp w -> head w&3 (32-col block), row-half w>>2
    wmma::fragment<wmma::accumulator, 16, 16, 16, float> oc[2][2];
    {
        const int hh = warp & 3;
        const int rp = warp >> 2;
        #pragma unroll
        for (int i = 0; i < 2; ++i)
            #pragma unroll
            for (int j = 0; j < 2; ++j) wmma::fill_fragment(oc[i][j], 0.f);
        #pragma unroll
        for (int ks = 0; ks < 4; ++ks) {
            wmma::fragment<wmma::matrix_a, 16, 16, 16, __half, wmma::row_major> fa[2];
            wmma::fragment<wmma::matrix_b, 16, 16, 16, __half, wmma::row_major> fb[2];
            #pragma unroll
            for (int i = 0; i < 2; ++i)
                wmma::load_matrix_sync(fa[i], Sh + hh*HB + (rp*32 + i*16)*SHS + ks*16, SHS);
            #pragma unroll
            for (int j = 0; j < 2; ++j)
                wmma::load_matrix_sync(fb[j], Vh + ks*16*AS + hh*32 + j*16, AS);
            #pragma unroll
            for (int i = 0; i < 2; ++i)
                #pragma unroll
                for (int j = 0; j < 2; ++j) wmma::mma_sync(oc[i][j], fa[i], fb[j], oc[i][j]);
        }
    }
    __syncthreads();        // Sh reads done -> overlay Ff
    {
        const int hh = warp & 3;
        const int rp = warp >> 2;
        #pragma unroll
        for (int i = 0; i < 2; ++i)
            #pragma unroll
            for (int j = 0; j < 2; ++j)
                wmma::store_matrix_sync(Ff + (rp*32 + i*16)*FS + hh*32 + j*16, oc[i][j], FS, wmma::mem_row_major);
    }
    __syncthreads();
    for (int idx = tid; idx < 2048; idx += 256) {
        const int r = idx >> 5, cg = idx & 31;
        const float4 v = *(const float4*)(Ff + r*FS + cg*4);
        __half* dst = Xh + r*AS + cg*4;
        dst[0] = __float2half(v.x); dst[1] = __float2half(v.y);
        dst[2] = __float2half(v.z); dst[3] = __float2half(v.w);
    }
    __syncthreads();

    // ---- Phase 4: proj via wmma + residual scatter ----
    for (int idx = tid; idx < 2048; idx += 256) {
        const int k = idx >> 4, u = idx & 15;
        *(uint4*)(Wc + k*AS + u*8) = *(const uint4*)(g_projwh + k*128 + u*8);
    }
    __syncthreads();
    {
        wmma::fragment<wmma::accumulator, 16, 16, 16, float> pc[2][2];
        #pragma unroll
        for (int i = 0; i < 2; ++i)
            #pragma unroll
            for (int j = 0; j < 2; ++j) wmma::fill_fragment(pc[i][j], 0.f);
        #pragma unroll
        for (int ks = 0; ks < 8; ++ks) {
            wmma::fragment<wmma::matrix_a, 16, 16, 16, __half, wmma::row_major> fa[2];
            wmma::fragment<wmma::matrix_b, 16, 16, 16, __half, wmma::row_major> fb[2];
            #pragma unroll
            for (int i = 0; i < 2; ++i)
                wmma::load_matrix_sync(fa[i], Xh + (rt2*32 + i*16)*AS + ks*16, AS);
            #pragma unroll
            for (int j = 0; j < 2; ++j)
                wmma::load_matrix_sync(fb[j], Wc + ks*16*AS + ct2*32 + j*16, AS);
            #pragma unroll
            for (int i = 0; i < 2; ++i)
                #pragma unroll
                for (int j = 0; j < 2; ++j) wmma::mma_sync(pc[i][j], fa[i], fb[j], pc[i][j]);
        }
        __syncthreads();    // Wc reads done -> overlay Ff
        #pragma unroll
        for (int i = 0; i < 2; ++i)
            #pragma unroll
            for (int j = 0; j < 2; ++j)
                wmma::store_matrix_sync(Ff + (rt2*32 + i*16)*FS + ct2*32 + j*16, pc[i][j], FS, wmma::mem_row_major);
    }
    __syncthreads();

    for (int idx = tid; idx < 2048; idx += 256) {
        const int r = idx >> 5, cg = idx & 31;
        const long base = (long)orow_s[r]*128;
        const float4 v  = *(const float4*)(Ff + r*FS + cg*4);
        const float4 pb = *(const float4*)(proj_b + cg*4);
        const float4 xin = *(const float4*)(inp + base + cg*4);
        float4 o;
        o.x = 0.5f*(v.x + pb.x) + xin.x;
        o.y = 0.5f*(v.y + pb.y) + xin.y;
        o.z = 0.5f*(v.z + pb.z) + xin.z;
        o.w = 0.5f*(v.w + pb.w) + xin.w;
        *(float4*)(out + base + cg*4) = o;
    }
}

// ---------------------------------------------------------------------------
// Kernel B v3: wmma fp16 MLP (32x32 warp tiles), fp16 weights, overlay. 3 CTA/SM.
// ---------------------------------------------------------------------------
__global__ void __launch_bounds__(256, 3) swin_mlp_kernel(
    const float* __restrict__ bb1, const float* __restrict__ bb2,
    const float* __restrict__ g2, const float* __restrict__ b2,
    float* __restrict__ io)
{
    extern __shared__ char smraw[];
    __half* A1 = (__half*)smraw;          // 64*AS
    __half* A2 = A1 + 64*AS;              // 64*AS
    char*   U  = (char*)(A2 + 64*AS);     // 34816B union
    __half* Wc = (__half*)U;
    float*  Ff = (float*)U;

    const int tid  = threadIdx.x;
    const int warp = tid >> 5, lane = tid & 31;
    const long row0 = (long)blockIdx.x * 64;

    {
        const float4 gv = *(const float4*)(g2 + lane*4);
        const float4 bv = *(const float4*)(b2 + lane*4);
        for (int t = warp*8; t < warp*8 + 8; ++t) {
            const float* row = io + (row0 + t)*128;
            const float4 x4 = *(const float4*)(row + lane*4);
            float s = x4.x + x4.y + x4.z + x4.w;
            float q = x4.x*x4.x + x4.y*x4.y + x4.z*x4.z + x4.w*x4.w;
            #pragma unroll
            for (int o = 16; o; o >>= 1) {
                s += __shfl_xor_sync(0xffffffffu, s, o);
                q += __shfl_xor_sync(0xffffffffu, q, o);
            }
            const float m = s * 0.0078125f;
            const float rstd = rsqrtf(q*0.0078125f - m*m + 1e-5f);
            __half* dst = A1 + t*AS + lane*4;
            dst[0] = __float2half((x4.x - m)*rstd*gv.x + bv.x);
            dst[1] = __float2half((x4.y - m)*rstd*gv.y + bv.y);
            dst[2] = __float2half((x4.z - m)*rstd*gv.z + bv.z);
            dst[3] = __float2half((x4.w - m)*rstd*gv.w + bv.w);
        }
    }

    const int rt2 = warp >> 2;   // 32-row half
    const int ct2 = warp & 3;    // 32-col quarter

    wmma::fragment<wmma::accumulator, 16, 16, 16, float> acc2[2][2];
    #pragma unroll
    for (int i = 0; i < 2; ++i)
        #pragma unroll
        for (int j = 0; j < 2; ++j) wmma::fill_fragment(acc2[i][j], 0.f);

    for (int nb = 0; nb < 4; ++nb) {
        __syncthreads();
        for (int idx = tid; idx < 2048; idx += 256) {
            const int k = idx >> 4, u = idx & 15;
            *(uint4*)(Wc + k*AS + u*8) = *(const uint4*)(g_w1h + k*512 + nb*128 + u*8);
        }
        __syncthreads();

        wmma::fragment<wmma::accumulator, 16, 16, 16, float> c1[2][2];
        #pragma unroll
        for (int i = 0; i < 2; ++i)
            #pragma unroll
            for (int j = 0; j < 2; ++j) wmma::fill_fragment(c1[i][j], 0.f);
        #pragma unroll
        for (int ks = 0; ks < 8; ++ks) {
            wmma::fragment<wmma::matrix_a, 16, 16, 16, __half, wmma::row_major> fa[2];
            wmma::fragment<wmma::matrix_b, 16, 16, 16, __half, wmma::row_major> fb[2];
            #pragma unroll
            for (int i = 0; i < 2; ++i)
                wmma::load_matrix_sync(fa[i], A1 + (rt2*32 + i*16)*AS + ks*16, AS);
            #pragma unroll
            for (int j = 0; j < 2; ++j)
                wmma::load_matrix_sync(fb[j], Wc + ks*16*AS + ct2*32 + j*16, AS);
            #pragma unroll
            for (int i = 0; i < 2; ++i)
                #pragma unroll
                for (int j = 0; j < 2; ++j) wmma::mma_sync(c1[i][j], fa[i], fb[j], c1[i][j]);
        }
        __syncthreads();
        #pragma unroll
        for (int i = 0; i < 2; ++i)
            #pragma unroll
            for (int j = 0; j < 2; ++j)
                wmma::store_matrix_sync(Ff + (rt2*32 + i*16)*FS + ct2*32 + j*16, c1[i][j], FS, wmma::mem_row_major);
        __syncthreads();

        for (int idx = tid; idx < 2048; idx += 256) {
            const int r = idx >> 5, cg = idx & 31;
            const float4 v = *(const float4*)(Ff + r*FS + cg*4);
            const float4 bv = *(const float4*)(bb1 + nb*128 + cg*4);
            float h0 = v.x + bv.x, h1 = v.y + bv.y, h2 = v.z + bv.z, h3 = v.w + bv.w;
            h0 = h0 * 0.5f * (1.f + erff(h0 * 0.70710678118654752f));
            h1 = h1 * 0.5f * (1.f + erff(h1 * 0.70710678118654752f));
            h2 = h2 * 0.5f * (1.f + erff(h2 * 0.70710678118654752f));
            h3 = h3 * 0.5f * (1.f + erff(h3 * 0.70710678118654752f));
            __half* dst = A2 + r*AS + cg*4;
            dst[0] = __float2half(h0); dst[1] = __float2half(h1);
            dst[2] = __float2half(h2); dst[3] = __float2half(h3);
        }
        __syncthreads();
        for (int idx = tid; idx < 2048; idx += 256) {
            const int k = idx >> 4, u = idx & 15;
            *(uint4*)(Wc + k*AS + u*8) = *(const uint4*)(g_w2h + (nb*128 + k)*128 + u*8);
        }
        __syncthreads();

        #pragma unroll
        for (int ks = 0; ks < 8; ++ks) {
            wmma::fragment<wmma::matrix_a, 16, 16, 16, __half, wmma::row_major> fa[2];
            wmma::fragment<wmma::matrix_b, 16, 16, 16, __half, wmma::row_major> fb[2];
            #pragma unroll
            for (int i = 0; i < 2; ++i)
                wmma::load_matrix_sync(fa[i], A2 + (rt2*32 + i*16)*AS + ks*16, AS);
            #pragma unroll
            for (int j = 0; j < 2; ++j)
                wmma::load_matrix_sync(fb[j], Wc + ks*16*AS + ct2*32 + j*16, AS);
            #pragma unroll
            for (int i = 0; i < 2; ++i)
                #pragma unroll
                for (int j = 0; j < 2; ++j) wmma::mma_sync(acc2[i][j], fa[i], fb[j], acc2[i][j]);
        }
    }

    __syncthreads();
    #pragma unroll
    for (int i = 0; i < 2; ++i)
        #pragma unroll
        for (int j = 0; j < 2; ++j)
            wmma::store_matrix_sync(Ff + (rt2*32 + i*16)*FS + ct2*32 + j*16, acc2[i][j], FS, wmma::mem_row_major);
    __syncthreads();

    for (int idx = tid; idx < 2048; idx += 256) {
        const int r = idx >> 5, cg = idx & 31;
        const float4 v  = *(const float4*)(Ff + r*FS + cg*4);
        const float4 bv = *(const float4*)(bb2 + cg*4);
        float* gp = io + (row0 + r)*128 + cg*4;
        const float4 xv = *(const float4*)gp;
        float4 o;
        o.x = 0.5f*(v.x + bv.x) + xv.x;
        o.y = 0.5f*(v.y + bv.y) + xv.y;
        o.z = 0.5f*(v.z + bv.z) + xv.z;
        o.w = 0.5f*(v.w + bv.w) + xv.w;
        *(float4*)gp = o;
    }
}

// ---------------------------------------------------------------------------
extern "C" void kernel_launch(void* const* d_in, const int* in_sizes, int n_in,
                              void* d_out, int out_size) {
    const float* inputs     = (const float*)d_in[0];
    const float* qkv_w      = (const float*)d_in[1];
    const float* proj_w     = (const float*)d_in[2];
    const float* proj_b     = (const float*)d_in[3];
    const float* bias_table = (const float*)d_in[4];
    const float* g1         = (const float*)d_in[5];
    const float* b1         = (const float*)d_in[6];
    const float* g2         = (const float*)d_in[7];
    const float* b2         = (const float*)d_in[8];
    const float* w1         = (const float*)d_in[9];
    const float* bb1        = (const float*)d_in[10];
    const float* w2         = (const float*)d_in[11];
    const float* bb2        = (const float*)d_in[12];
    float* out = (float*)d_out;

    // A: Xh..Vh (4*64*AS halfs) + U (36864) + tables
    const int smemA = (4*64*AS)*2 + 36864 + 484*4 + 64*4 + 64*4;   // 108944 B
    const int smemB = (2*64*AS)*2 + 34816;                          // 69632 B

    cudaFuncSetAttribute(swin_attn_kernel, cudaFuncAttributeMaxDynamicSharedMemorySize, smemA);
    cudaFuncSetAttribute(swin_mlp_kernel,  cudaFuncAttributeMaxDynamicSharedMemorySize, smemB);

    cvt_weights_kernel<<<192, 256>>>(qkv_w, proj_w, w1, w2);
    swin_attn_kernel<<<4096, 256, smemA>>>(inputs, proj_b, bias_table, g1, b1, out);
    swin_mlp_kernel<<<4096, 256, smemB>>>(bb1, bb2, g2, b2, out);
}

// round 12
// speedup vs baseline: 7.6466x; 1.0792x over previous
#include <cuda_runtime.h>
#include <cuda_fp16.h>
#include <mma.h>
#include <math.h>
#include <stdint.h>
#include <cstdint>

using namespace nvcuda;

#define AS 136    // fp16 tile stride (halfs, mult of 8)
#define FS 136    // f32 scratch stride (floats)
#define HS2 136   // half scratch stride (halfs)
#define SHS 72    // fp16 score row stride (halfs, mult of 8)
#define HB (64*SHS)  // per-head S block (halfs)

// fp16 pre-converted weights (written by cvt_weights_kernel each launch)
// Q columns of qkv_w are pre-scaled by 1/sqrt(HD).
__device__ __align__(16) __half g_qkvwh[128*384];
__device__ __align__(16) __half g_projwh[128*128];
__device__ __align__(16) __half g_w1h[128*512];
__device__ __align__(16) __half g_w2h[512*128];

// ---------------------------------------------------------------------------
__global__ void cvt_weights_kernel(const float* __restrict__ qkv_w,
                                   const float* __restrict__ proj_w,
                                   const float* __restrict__ w1,
                                   const float* __restrict__ w2)
{
    const int i4 = (blockIdx.x*256 + threadIdx.x) * 4;   // grid 192 -> 196608
    const float* src; __half* dst; int off;
    float scale = 1.f;
    if (i4 < 49152) {
        src = qkv_w;  dst = g_qkvwh;  off = i4;
        if ((off % 384) < 128) scale = 0.17677669529663687f;   // fold qscale into Q
    }
    else if (i4 < 65536)  { src = proj_w; dst = g_projwh; off = i4 - 49152; }
    else if (i4 < 131072) { src = w1;     dst = g_w1h;    off = i4 - 65536; }
    else                  { src = w2;     dst = g_w2h;    off = i4 - 131072; }
    const float4 v = *(const float4*)(src + off);
    dst[off+0] = __float2half(v.x*scale); dst[off+1] = __float2half(v.y*scale);
    dst[off+2] = __float2half(v.z*scale); dst[off+3] = __float2half(v.w*scale);
}

// ---------------------------------------------------------------------------
// Kernel A v5: LN1 -> QKV(wmma, half acc, direct store) -> all-heads attention
// (fp16 S, reg softmax, PV half acc direct to Xh) -> proj(half acc) -> scatter.
// 2 CTA/SM.
// ---------------------------------------------------------------------------
__global__ void __launch_bounds__(256, 2) swin_attn_kernel(
    const float* __restrict__ inp,
    const float* __restrict__ proj_b,
    const float* __restrict__ bias_table,
    const float* __restrict__ g1,
    const float* __restrict__ b1,
    float* __restrict__ out)
{
    extern __shared__ char sma[];
    __half* Xh = (__half*)sma;            // 64*AS (LN'd X; later O fp16)
    __half* Qh = Xh + 64*AS;
    __half* Kh = Qh + 64*AS;
    __half* Vh = Kh + 64*AS;
    char*   U  = (char*)(Vh + 64*AS);     // 36864B union: Wc / Sh / Ph2
    __half* Wc  = (__half*)U;             // 128*AS halfs (34816B)
    __half* Sh  = (__half*)U;             // 4*HB halfs (36864B)
    __half* Ph2 = (__half*)U;             // 64*HS2 halfs proj scratch (17408B)
    float*  bias_s = (float*)(U + 36864); // 484
    int*    lab_s  = (int*)(bias_s + 484);
    int*    orow_s = lab_s + 64;

    const int tid = threadIdx.x;
    const int warp = tid >> 5, lane = tid & 31;
    const int wblk = blockIdx.x;
    const int bb = wblk >> 9;
    const int wi = wblk & 511;
    const int gx = wi >> 6, gy = (wi >> 3) & 7, gz = wi & 7;

    for (int i = tid; i < 484; i += 256) bias_s[i] = bias_table[i];

    if (tid < 64) {
        const int lx = tid >> 4, ly = (tid >> 2) & 3, lz = tid & 3;
        const int px = gx*4 + lx, py = gy*4 + ly, pz = gz*4 + lz;
        const int ox = (px + 2) & 31, oy = (py + 2) & 31, oz = (pz + 2) & 31;
        orow_s[tid] = ((bb*32 + ox)*32 + oy)*32 + oz;
        const int labx = px < 28 ? 0 : (px < 30 ? 1 : 2);
        const int laby = py < 28 ? 0 : (py < 30 ? 1 : 2);
        const int labz = pz < 28 ? 0 : (pz < 30 ? 1 : 2);
        lab_s[tid] = labx*9 + laby*3 + labz;
    }
    __syncthreads();

    // ---- Phase 1: LayerNorm -> fp16 Xh ----
    {
        const float4 gv = *(const float4*)(g1 + lane*4);
        const float4 bv = *(const float4*)(b1 + lane*4);
        for (int t = warp*8; t < warp*8 + 8; ++t) {
            const float* row = inp + (long)orow_s[t]*128;
            const float4 x4 = *(const float4*)(row + lane*4);
            float s = x4.x + x4.y + x4.z + x4.w;
            float q = x4.x*x4.x + x4.y*x4.y + x4.z*x4.z + x4.w*x4.w;
            #pragma unroll
            for (int o = 16; o; o >>= 1) {
                s += __shfl_xor_sync(0xffffffffu, s, o);
                q += __shfl_xor_sync(0xffffffffu, q, o);
            }
            const float m = s * 0.0078125f;
            const float rstd = rsqrtf(q*0.0078125f - m*m + 1e-5f);
            __half* dst = Xh + t*AS + lane*4;
            dst[0] = __float2half((x4.x - m)*rstd*gv.x + bv.x);
            dst[1] = __float2half((x4.y - m)*rstd*gv.y + bv.y);
            dst[2] = __float2half((x4.z - m)*rstd*gv.z + bv.z);
            dst[3] = __float2half((x4.w - m)*rstd*gv.w + bv.w);
        }
    }

    const int rt2 = warp >> 2;            // 32-row half (0..1)
    const int ct2 = warp & 3;             // 32-col quarter (0..3)

    // ---- Phase 2: QKV via wmma, half accumulators, direct fp16 stores ----
    for (int c = 0; c < 3; ++c) {
        __syncthreads();    // prev Wc reads (or tables) done
        for (int idx = tid; idx < 2048; idx += 256) {
            const int k = idx >> 4, u = idx & 15;
            *(uint4*)(Wc + k*AS + u*8) = *(const uint4*)(g_qkvwh + k*384 + c*128 + u*8);
        }
        __syncthreads();
        wmma::fragment<wmma::accumulator, 16, 16, 16, __half> c1[2][2];
        #pragma unroll
        for (int i = 0; i < 2; ++i)
            #pragma unroll
            for (int j = 0; j < 2; ++j) wmma::fill_fragment(c1[i][j], __float2half(0.f));
        #pragma unroll
        for (int ks = 0; ks < 8; ++ks) {
            wmma::fragment<wmma::matrix_a, 16, 16, 16, __half, wmma::row_major> fa[2];
            wmma::fragment<wmma::matrix_b, 16, 16, 16, __half, wmma::row_major> fb[2];
            #pragma unroll
            for (int i = 0; i < 2; ++i)
                wmma::load_matrix_sync(fa[i], Xh + (rt2*32 + i*16)*AS + ks*16, AS);
            #pragma unroll
            for (int j = 0; j < 2; ++j)
                wmma::load_matrix_sync(fb[j], Wc + ks*16*AS + ct2*32 + j*16, AS);
            #pragma unroll
            for (int i = 0; i < 2; ++i)
                #pragma unroll
                for (int j = 0; j < 2; ++j) wmma::mma_sync(c1[i][j], fa[i], fb[j], c1[i][j]);
        }
        __half* dest = (c == 0) ? Qh : (c == 1) ? Kh : Vh;
        #pragma unroll
        for (int i = 0; i < 2; ++i)
            #pragma unroll
            for (int j = 0; j < 2; ++j)
                wmma::store_matrix_sync(dest + (rt2*32 + i*16)*AS + ct2*32 + j*16, c1[i][j], AS, wmma::mem_row_major);
    }
    __syncthreads();        // Q/K/V visible; Wc reads done -> U reusable as Sh

    // ---- Phase 3: all-heads attention ----
    {
        const int h = warp >> 1;
        const int p = warp & 1;
        wmma::fragment<wmma::accumulator, 16, 16, 16, __half> sc[2][4];
        #pragma unroll
        for (int i = 0; i < 2; ++i)
            #pragma unroll
            for (int j = 0; j < 4; ++j) wmma::fill_fragment(sc[i][j], __float2half(0.f));
        #pragma unroll
        for (int ks = 0; ks < 2; ++ks) {
            wmma::fragment<wmma::matrix_a, 16, 16, 16, __half, wmma::row_major> fa[2];
            wmma::fragment<wmma::matrix_b, 16, 16, 16, __half, wmma::col_major> fb[4];
            #pragma unroll
            for (int i = 0; i < 2; ++i)
                wmma::load_matrix_sync(fa[i], Qh + (p*32 + i*16)*AS + h*32 + ks*16, AS);
            #pragma unroll
            for (int j = 0; j < 4; ++j)
                wmma::load_matrix_sync(fb[j], Kh + j*16*AS + h*32 + ks*16, AS);
            #pragma unroll
            for (int i = 0; i < 2; ++i)
                #pragma unroll
                for (int j = 0; j < 4; ++j) wmma::mma_sync(sc[i][j], fa[i], fb[j], sc[i][j]);
        }
        #pragma unroll
        for (int i = 0; i < 2; ++i)
            #pragma unroll
            for (int j = 0; j < 4; ++j)
                wmma::store_matrix_sync(Sh + h*HB + (p*32 + i*16)*SHS + j*16, sc[i][j], SHS, wmma::mem_row_major);
    }
    __syncthreads();

    // softmax: one thread per (head, row), fully in registers (half2)
    {
        const int shh = tid >> 6;
        const int si  = tid & 63;
        __half* Srow = Sh + shh*HB + si*SHS;
        const int li = lab_s[si];
        const int lxi = si >> 4, lyi = (si >> 2) & 3, lzi = si & 3;
        half2 av[32];
        float mx = -1e30f;
        #pragma unroll
        for (int t = 0; t < 32; ++t) {
            const int j0 = 2*t;
            const float2 s2 = __half22float2(*(half2*)(Srow + j0));
            const int lxj = j0 >> 4, lyj = (j0 >> 2) & 3, lzj = j0 & 3;
            const int brow = 11*(lxi - lxj + 3) + (lyi - lyj + 3) + (lzi - lzj + 3);
            float a0 = s2.x + bias_s[brow*4 + shh];
            float a1 = s2.y + bias_s[(brow-1)*4 + shh];
            if (lab_s[j0]   != li) a0 -= 100.f;
            if (lab_s[j0+1] != li) a1 -= 100.f;
            mx = fmaxf(mx, fmaxf(a0, a1));
            av[t] = __floats2half2_rn(a0, a1);
        }
        const half2 mx2 = __float2half2_rn(mx);
        float sum = 0.f;
        #pragma unroll
        for (int t = 0; t < 32; ++t) {
            av[t] = h2exp(__hsub2(av[t], mx2));
            const float2 e2 = __half22float2(av[t]);
            sum += e2.x + e2.y;
        }
        const half2 inv2 = __float2half2_rn(1.f / sum);
        #pragma unroll
        for (int t = 0; t < 32; ++t)
            *(half2*)(Srow + 2*t) = __hmul2(av[t], inv2);
    }
    __syncthreads();

    // PV (all heads): half acc, store direct into Xh
    {
        const int hh = warp & 3;
        const int rp = warp >> 2;
        wmma::fragment<wmma::accumulator, 16, 16, 16, __half> oc[2][2];
        #pragma unroll
        for (int i = 0; i < 2; ++i)
            #pragma unroll
            for (int j = 0; j < 2; ++j) wmma::fill_fragment(oc[i][j], __float2half(0.f));
        #pragma unroll
        for (int ks = 0; ks < 4; ++ks) {
            wmma::fragment<wmma::matrix_a, 16, 16, 16, __half, wmma::row_major> fa[2];
            wmma::fragment<wmma::matrix_b, 16, 16, 16, __half, wmma::row_major> fb[2];
            #pragma unroll
            for (int i = 0; i < 2; ++i)
                wmma::load_matrix_sync(fa[i], Sh + hh*HB + (rp*32 + i*16)*SHS + ks*16, SHS);
            #pragma unroll
            for (int j = 0; j < 2; ++j)
                wmma::load_matrix_sync(fb[j], Vh + ks*16*AS + hh*32 + j*16, AS);
            #pragma unroll
            for (int i = 0; i < 2; ++i)
                #pragma unroll
                for (int j = 0; j < 2; ++j) wmma::mma_sync(oc[i][j], fa[i], fb[j], oc[i][j]);
        }
        #pragma unroll
        for (int i = 0; i < 2; ++i)
            #pragma unroll
            for (int j = 0; j < 2; ++j)
                wmma::store_matrix_sync(Xh + (rp*32 + i*16)*AS + hh*32 + j*16, oc[i][j], AS, wmma::mem_row_major);
    }
    __syncthreads();        // Sh reads done -> U reusable as Wc; Xh stores visible

    // ---- Phase 4: proj via wmma (half acc) + residual scatter ----
    for (int idx = tid; idx < 2048; idx += 256) {
        const int k = idx >> 4, u = idx & 15;
        *(uint4*)(Wc + k*AS + u*8) = *(const uint4*)(g_projwh + k*128 + u*8);
    }
    __syncthreads();
    {
        wmma::fragment<wmma::accumulator, 16, 16, 16, __half> pc[2][2];
        #pragma unroll
        for (int i = 0; i < 2; ++i)
            #pragma unroll
            for (int j = 0; j < 2; ++j) wmma::fill_fragment(pc[i][j], __float2half(0.f));
        #pragma unroll
        for (int ks = 0; ks < 8; ++ks) {
            wmma::fragment<wmma::matrix_a, 16, 16, 16, __half, wmma::row_major> fa[2];
            wmma::fragment<wmma::matrix_b, 16, 16, 16, __half, wmma::row_major> fb[2];
            #pragma unroll
            for (int i = 0; i < 2; ++i)
                wmma::load_matrix_sync(fa[i], Xh + (rt2*32 + i*16)*AS + ks*16, AS);
            #pragma unroll
            for (int j = 0; j < 2; ++j)
                wmma::load_matrix_sync(fb[j], Wc + ks*16*AS + ct2*32 + j*16, AS);
            #pragma unroll
            for (int i = 0; i < 2; ++i)
                #pragma unroll
                for (int j = 0; j < 2; ++j) wmma::mma_sync(pc[i][j], fa[i], fb[j], pc[i][j]);
        }
        __syncthreads();    // Wc reads done -> overlay Ph2
        #pragma unroll
        for (int i = 0; i < 2; ++i)
            #pragma unroll
            for (int j = 0; j < 2; ++j)
                wmma::store_matrix_sync(Ph2 + (rt2*32 + i*16)*HS2 + ct2*32 + j*16, pc[i][j], HS2, wmma::mem_row_major);
    }
    __syncthreads();

    for (int idx = tid; idx < 2048; idx += 256) {
        const int r = idx >> 5, cg = idx & 31;
        const long base = (long)orow_s[r]*128;
        const half2 v01 = *(half2*)(Ph2 + r*HS2 + cg*4);
        const half2 v23 = *(half2*)(Ph2 + r*HS2 + cg*4 + 2);
        const float2 f01 = __half22float2(v01);
        const float2 f23 = __half22float2(v23);
        const float4 pb = *(const float4*)(proj_b + cg*4);
        const float4 xin = *(const float4*)(inp + base + cg*4);
        float4 o;
        o.x = 0.5f*(f01.x + pb.x) + xin.x;
        o.y = 0.5f*(f01.y + pb.y) + xin.y;
        o.z = 0.5f*(f23.x + pb.z) + xin.z;
        o.w = 0.5f*(f23.y + pb.w) + xin.w;
        *(float4*)(out + base + cg*4) = o;
    }
}

// ---------------------------------------------------------------------------
// Kernel B v5: wmma fp16 MLP; gemm1 half acc + half scratch, gemm2 f32 acc.
// 3 CTA/SM.
// ---------------------------------------------------------------------------
__global__ void __launch_bounds__(256, 3) swin_mlp_kernel(
    const float* __restrict__ bb1, const float* __restrict__ bb2,
    const float* __restrict__ g2, const float* __restrict__ b2,
    float* __restrict__ io)
{
    extern __shared__ char smraw[];
    __half* A1 = (__half*)smraw;          // 64*AS
    __half* A2 = A1 + 64*AS;              // 64*AS
    char*   U  = (char*)(A2 + 64*AS);     // 34816B union
    __half* Wc = (__half*)U;              // weights
    __half* Hs = (__half*)U;              // half scratch (64*HS2)
    float*  Ff = (float*)U;               // f32 scratch (final epilogue)

    const int tid  = threadIdx.x;
    const int warp = tid >> 5, lane = tid & 31;
    const long row0 = (long)blockIdx.x * 64;

    {
        const float4 gv = *(const float4*)(g2 + lane*4);
        const float4 bv = *(const float4*)(b2 + lane*4);
        for (int t = warp*8; t < warp*8 + 8; ++t) {
            const float* row = io + (row0 + t)*128;
            const float4 x4 = *(const float4*)(row + lane*4);
            float s = x4.x + x4.y + x4.z + x4.w;
            float q = x4.x*x4.x + x4.y*x4.y + x4.z*x4.z + x4.w*x4.w;
            #pragma unroll
            for (int o = 16; o; o >>= 1) {
                s += __shfl_xor_sync(0xffffffffu, s, o);
                q += __shfl_xor_sync(0xffffffffu, q, o);
            }
            const float m = s * 0.0078125f;
            const float rstd = rsqrtf(q*0.0078125f - m*m + 1e-5f);
            __half* dst = A1 + t*AS + lane*4;
            dst[0] = __float2half((x4.x - m)*rstd*gv.x + bv.x);
            dst[1] = __float2half((x4.y - m)*rstd*gv.y + bv.y);
            dst[2] = __float2half((x4.z - m)*rstd*gv.z + bv.z);
            dst[3] = __float2half((x4.w - m)*rstd*gv.w + bv.w);
        }
    }

    const int rt2 = warp >> 2;   // 32-row half
    const int ct2 = warp & 3;    // 32-col quarter

    wmma::fragment<wmma::accumulator, 16, 16, 16, float> acc2[2][2];
    #pragma unroll
    for (int i = 0; i < 2; ++i)
        #pragma unroll
        for (int j = 0; j < 2; ++j) wmma::fill_fragment(acc2[i][j], 0.f);

    for (int nb = 0; nb < 4; ++nb) {
        __syncthreads();    // prev gemm2 Wc reads done
        for (int idx = tid; idx < 2048; idx += 256) {
            const int k = idx >> 4, u = idx & 15;
            *(uint4*)(Wc + k*AS + u*8) = *(const uint4*)(g_w1h + k*512 + nb*128 + u*8);
        }
        __syncthreads();

        wmma::fragment<wmma::accumulator, 16, 16, 16, __half> c1[2][2];
        #pragma unroll
        for (int i = 0; i < 2; ++i)
            #pragma unroll
            for (int j = 0; j < 2; ++j) wmma::fill_fragment(c1[i][j], __float2half(0.f));
        #pragma unroll
        for (int ks = 0; ks < 8; ++ks) {
            wmma::fragment<wmma::matrix_a, 16, 16, 16, __half, wmma::row_major> fa[2];
            wmma::fragment<wmma::matrix_b, 16, 16, 16, __half, wmma::row_major> fb[2];
            #pragma unroll
            for (int i = 0; i < 2; ++i)
                wmma::load_matrix_sync(fa[i], A1 + (rt2*32 + i*16)*AS + ks*16, AS);
            #pragma unroll
            for (int j = 0; j < 2; ++j)
                wmma::load_matrix_sync(fb[j], Wc + ks*16*AS + ct2*32 + j*16, AS);
            #pragma unroll
            for (int i = 0; i < 2; ++i)
                #pragma unroll
                for (int j = 0; j < 2; ++j) wmma::mma_sync(c1[i][j], fa[i], fb[j], c1[i][j]);
        }
        __syncthreads();    // Wc reads done -> overlay Hs
        #pragma unroll
        for (int i = 0; i < 2; ++i)
            #pragma unroll
            for (int j = 0; j < 2; ++j)
                wmma::store_matrix_sync(Hs + (rt2*32 + i*16)*HS2 + ct2*32 + j*16, c1[i][j], HS2, wmma::mem_row_major);
        __syncthreads();

        // bias + exact GELU -> fp16 A2
        for (int idx = tid; idx < 2048; idx += 256) {
            const int r = idx >> 5, cg = idx & 31;
            const half2 v01 = *(half2*)(Hs + r*HS2 + cg*4);
            const half2 v23 = *(half2*)(Hs + r*HS2 + cg*4 + 2);
            const float2 f01 = __half22float2(v01);
            const float2 f23 = __half22float2(v23);
            const float4 bv = *(const float4*)(bb1 + nb*128 + cg*4);
            float h0 = f01.x + bv.x, h1 = f01.y + bv.y, h2 = f23.x + bv.z, h3 = f23.y + bv.w;
            h0 = h0 * 0.5f * (1.f + erff(h0 * 0.70710678118654752f));
            h1 = h1 * 0.5f * (1.f + erff(h1 * 0.70710678118654752f));
            h2 = h2 * 0.5f * (1.f + erff(h2 * 0.70710678118654752f));
            h3 = h3 * 0.5f * (1.f + erff(h3 * 0.70710678118654752f));
            __half* dst = A2 + r*AS + cg*4;
            dst[0] = __float2half(h0); dst[1] = __float2half(h1);
            dst[2] = __float2half(h2); dst[3] = __float2half(h3);
        }
        __syncthreads();    // Hs reads done -> overlay Wc (w2 chunk)
        for (int idx = tid; idx < 2048; idx += 256) {
            const int k = idx >> 4, u = idx & 15;
            *(uint4*)(Wc + k*AS + u*8) = *(const uint4*)(g_w2h + (nb*128 + k)*128 + u*8);
        }
        __syncthreads();

        #pragma unroll
        for (int ks = 0; ks < 8; ++ks) {
            wmma::fragment<wmma::matrix_a, 16, 16, 16, __half, wmma::row_major> fa[2];
            wmma::fragment<wmma::matrix_b, 16, 16, 16, __half, wmma::row_major> fb[2];
            #pragma unroll
            for (int i = 0; i < 2; ++i)
                wmma::load_matrix_sync(fa[i], A2 + (rt2*32 + i*16)*AS + ks*16, AS);
            #pragma unroll
            for (int j = 0; j < 2; ++j)
                wmma::load_matrix_sync(fb[j], Wc + ks*16*AS + ct2*32 + j*16, AS);
            #pragma unroll
            for (int i = 0; i < 2; ++i)
                #pragma unroll
                for (int j = 0; j < 2; ++j) wmma::mma_sync(acc2[i][j], fa[i], fb[j], acc2[i][j]);
        }
    }

    __syncthreads();        // Wc reads done -> overlay Ff
    #pragma unroll
    for (int i = 0; i < 2; ++i)
        #pragma unroll
        for (int j = 0; j < 2; ++j)
            wmma::store_matrix_sync(Ff + (rt2*32 + i*16)*FS + ct2*32 + j*16, acc2[i][j], FS, wmma::mem_row_major);
    __syncthreads();

    for (int idx = tid; idx < 2048; idx += 256) {
        const int r = idx >> 5, cg = idx & 31;
        const float4 v  = *(const float4*)(Ff + r*FS + cg*4);
        const float4 bv = *(const float4*)(bb2 + cg*4);
        float* gp = io + (row0 + r)*128 + cg*4;
        const float4 xv = *(const float4*)gp;
        float4 o;
        o.x = 0.5f*(v.x + bv.x) + xv.x;
        o.y = 0.5f*(v.y + bv.y) + xv.y;
        o.z = 0.5f*(v.z + bv.z) + xv.z;
        o.w = 0.5f*(v.w + bv.w) + xv.w;
        *(float4*)gp = o;
    }
}

// ---------------------------------------------------------------------------
extern "C" void kernel_launch(void* const* d_in, const int* in_sizes, int n_in,
                              void* d_out, int out_size) {
    const float* inputs     = (const float*)d_in[0];
    const float* qkv_w      = (const float*)d_in[1];
    const float* proj_w     = (const float*)d_in[2];
    const float* proj_b     = (const float*)d_in[3];
    const float* bias_table = (const float*)d_in[4];
    const float* g1         = (const float*)d_in[5];
    const float* b1         = (const float*)d_in[6];
    const float* g2         = (const float*)d_in[7];
    const float* b2         = (const float*)d_in[8];
    const float* w1         = (const float*)d_in[9];
    const float* bb1        = (const float*)d_in[10];
    const float* w2         = (const float*)d_in[11];
    const float* bb2        = (const float*)d_in[12];
    float* out = (float*)d_out;

    const int smemA = (4*64*AS)*2 + 36864 + 484*4 + 64*4 + 64*4;   // 108944 B
    const int smemB = (2*64*AS)*2 + 34816;                          // 69632 B

    cudaFuncSetAttribute(swin_attn_kernel, cudaFuncAttributeMaxDynamicSharedMemorySize, smemA);
    cudaFuncSetAttribute(swin_mlp_kernel,  cudaFuncAttributeMaxDynamicSharedMemorySize, smemB);

    cvt_weights_kernel<<<192, 256>>>(qkv_w, proj_w, w1, w2);
    swin_attn_kernel<<<4096, 256, smemA>>>(inputs, proj_b, bias_table, g1, b1, out);
    swin_mlp_kernel<<<4096, 256, smemB>>>(bb1, bb2, g2, b2, out);
}